// round 9
// baseline (speedup 1.0000x reference)
#include <cuda_runtime.h>
#include <cuda_bf16.h>
#include <cstdint>

#define N_NODES 50000
#define N_EDGES 800000
#define BN_EPS 1e-5f

// ---------------- device scratch (no allocations allowed) ----------------
__device__ float g_h[(size_t)N_NODES * 128];
__device__ float g_agg[(size_t)N_NODES * 128];
__device__ float g_dinv[N_NODES];
__device__ int   g_rowptr[N_NODES + 1];
__device__ int   g_cursor[N_NODES];
__device__ int   g_csr[N_EDGES];
__device__ int   g_cnt[N_NODES];
__device__ float g_bnsum[3][128];
__device__ float g_bnsq[3][128];
__device__ float g_scale[128];
__device__ float g_shift[128];
// bf16 split weights, transposed to B[n][k] row-major (k contiguous, K=128).
// L1:0 L2:16384 L3:32768 (128x128), L4:49152 (64x128)
__device__ __nv_bfloat16 g_whi[57344];
__device__ __nv_bfloat16 g_wlo[57344];

// ---------------- helpers ----------------
__device__ __forceinline__ uint32_t packbf(float a, float b) {
    __nv_bfloat162 t = __floats2bfloat162_rn(a, b);
    return *(uint32_t*)&t;
}

__device__ __forceinline__ void ldsm4(uint32_t* r, uint32_t addr) {
    asm volatile("ldmatrix.sync.aligned.m8n8.x4.shared.b16 {%0,%1,%2,%3}, [%4];"
                 : "=r"(r[0]), "=r"(r[1]), "=r"(r[2]), "=r"(r[3]) : "r"(addr));
}

__device__ __forceinline__ void mma16816(float* c, const uint32_t* a, const uint32_t* b) {
    asm volatile(
        "mma.sync.aligned.m16n8k16.row.col.f32.bf16.bf16.f32 "
        "{%0,%1,%2,%3}, {%4,%5,%6,%7}, {%8,%9}, {%0,%1,%2,%3};"
        : "+f"(c[0]), "+f"(c[1]), "+f"(c[2]), "+f"(c[3])
        : "r"(a[0]), "r"(a[1]), "r"(a[2]), "r"(a[3]), "r"(b[0]), "r"(b[1]));
}

__device__ __forceinline__ void wsplit(const float* W, __nv_bfloat16* hi,
                                       __nv_bfloat16* lo, int NB, int idx) {
    int k = idx / NB, n = idx % NB;
    float v = W[idx];
    __nv_bfloat16 h = __float2bfloat16(v);
    __nv_bfloat16 l = __float2bfloat16(v - __bfloat162float(h));
    hi[n * 128 + k] = h;
    lo[n * 128 + k] = l;
}

// ---------------- fused prep: weight split x4, cnt zero, BN slot zero ----------------
__global__ void k_prep(const float* __restrict__ W1, const float* __restrict__ W2,
                       const float* __restrict__ W3, const float* __restrict__ W4) {
    int g = blockIdx.x * blockDim.x + threadIdx.x;
    int stride = gridDim.x * blockDim.x;
    for (int i = g; i < N_NODES; i += stride) g_cnt[i] = 0;
    for (int i = g; i < 3 * 128; i += stride) {
        g_bnsum[i >> 7][i & 127] = 0.f;
        g_bnsq[i >> 7][i & 127] = 0.f;
    }
    for (int i = g; i < 16384; i += stride) wsplit(W1, g_whi + 0,     g_wlo + 0,     128, i);
    for (int i = g; i < 16384; i += stride) wsplit(W2, g_whi + 16384, g_wlo + 16384, 128, i);
    for (int i = g; i < 16384; i += stride) wsplit(W3, g_whi + 32768, g_wlo + 32768, 128, i);
    for (int i = g; i < 8192;  i += stride) wsplit(W4, g_whi + 49152, g_wlo + 49152, 64,  i);
}

// ---------------- graph preprocessing ----------------
__global__ void k_count(const int* __restrict__ dst) {
    int e = blockIdx.x * blockDim.x + threadIdx.x;
    if (e < N_EDGES) atomicAdd(&g_cnt[dst[e]], 1);
}

__global__ void k_scan() {
    const int T = 1024;
    const int CH = (N_NODES + T - 1) / T;
    int t = threadIdx.x;
    int s = t * CH;
    int e = min(s + CH, N_NODES);
    int local = 0;
    for (int i = s; i < e; i++) local += g_cnt[i];

    int lane = t & 31, wid = t >> 5;
    int v = local;
    #pragma unroll
    for (int o = 1; o < 32; o <<= 1) {
        int u = __shfl_up_sync(0xFFFFFFFFu, v, o);
        if (lane >= o) v += u;
    }
    __shared__ int wsum[32];
    if (lane == 31) wsum[wid] = v;
    __syncthreads();
    if (wid == 0) {
        int wv = wsum[lane];
        #pragma unroll
        for (int o = 1; o < 32; o <<= 1) {
            int u = __shfl_up_sync(0xFFFFFFFFu, wv, o);
            if (lane >= o) wv += u;
        }
        wsum[lane] = wv;
    }
    __syncthreads();
    int incl = v + (wid > 0 ? wsum[wid - 1] : 0);
    int run = incl - local;

    for (int i = s; i < e; i++) {
        int c = g_cnt[i];
        g_rowptr[i] = run;
        g_cursor[i] = run;
        g_dinv[i]   = rsqrtf((float)c + 1.0f);
        run += c;
    }
    if (t == T - 1) g_rowptr[N_NODES] = run;
}

__global__ void k_scatter(const int* __restrict__ src, const int* __restrict__ dst) {
    int e = blockIdx.x * blockDim.x + threadIdx.x;
    if (e < N_EDGES) {
        int d = dst[e];
        int p = atomicAdd(&g_cursor[d], 1);
        g_csr[p] = src[e];
    }
}

// ---------------- HMMA GEMM: H[N,NBTOT] = act(X[N,128]) @ W[128,NBTOT] ----------------
// Double-bf16: D = Ahi*Bhi + Ahi*Blo + Alo*Bhi, fp32 accumulators.
// CTA tile: 128 rows x 64 cols (blockIdx.y = col tile). 512 threads, 16 warps.
// Warp w: rows (w&7)*16, local cols (w>>3)*32. smem 104KB -> 2 CTAs/SM.
template <int NBTOT>
__global__ void __launch_bounds__(512) k_mma_gemm(
    const float* __restrict__ X,
    const __nv_bfloat16* __restrict__ Bhi_g,
    const __nv_bfloat16* __restrict__ Blo_g,
    float* __restrict__ H, int useBN) {
    constexpr int AS = 136;   // smem row stride (bf16) -> conflict-free ldmatrix
    constexpr int NT = 4;     // n8-tiles per warp (32 cols / 8)

    extern __shared__ __nv_bfloat16 sm[];
    __nv_bfloat16* Ah = sm;                    // 128*AS
    __nv_bfloat16* Al = Ah + 128 * AS;         // 128*AS
    __nv_bfloat16* Bh = Al + 128 * AS;         // 64*AS
    __nv_bfloat16* Bl = Bh + 64 * AS;          // 64*AS

    int tid = threadIdx.x, lane = tid & 31, w = tid >> 5;
    int rb = blockIdx.x * 128;
    int cb = blockIdx.y * 64;

    // stage B slice [cb, cb+64) (pre-split bf16, [n][k] k-contiguous), 16B chunks
    for (int c = tid; c < 64 * 16; c += 512) {
        int n = c >> 4, s = c & 15;
        *(uint4*)(Bh + n * AS + s * 8) = ((const uint4*)Bhi_g)[(cb + n) * 16 + s];
        *(uint4*)(Bl + n * AS + s * 8) = ((const uint4*)Blo_g)[(cb + n) * 16 + s];
    }

    // stage A: load fp32, optional BN+ReLU, split into hi/lo bf16
    #pragma unroll
    for (int i = 0; i < 8; i++) {
        int idx = tid + i * 512;         // 0..4095
        int row = idx >> 5, q = idx & 31;
        int r = rb + row;
        float4 v = make_float4(0.f, 0.f, 0.f, 0.f);
        if (r < N_NODES) {
            v = ((const float4*)X)[(size_t)r * 32 + q];
            if (useBN) {
                int k = q * 4;
                v.x = fmaxf(fmaf(v.x, g_scale[k + 0], g_shift[k + 0]), 0.f);
                v.y = fmaxf(fmaf(v.y, g_scale[k + 1], g_shift[k + 1]), 0.f);
                v.z = fmaxf(fmaf(v.z, g_scale[k + 2], g_shift[k + 2]), 0.f);
                v.w = fmaxf(fmaf(v.w, g_scale[k + 3], g_shift[k + 3]), 0.f);
            }
        }
        float hx = __bfloat162float(__float2bfloat16(v.x));
        float hy = __bfloat162float(__float2bfloat16(v.y));
        float hz = __bfloat162float(__float2bfloat16(v.z));
        float hw = __bfloat162float(__float2bfloat16(v.w));
        uint32_t h01 = packbf(v.x, v.y), h23 = packbf(v.z, v.w);
        uint32_t l01 = packbf(v.x - hx, v.y - hy), l23 = packbf(v.z - hz, v.w - hw);
        *(uint2*)(Ah + row * AS + q * 4) = make_uint2(h01, h23);
        *(uint2*)(Al + row * AS + q * 4) = make_uint2(l01, l23);
    }
    __syncthreads();

    int mrow = (w & 7) * 16;
    int ncol = (w >> 3) * 32;   // local col offset within the 64-col slice

    // ldmatrix lane addresses. A x4: lanes 0-15 rows 0-15 @k0, 16-31 rows 0-15 @k8.
    uint32_t offA = ((mrow + (lane & 15)) * AS + ((lane >> 4) << 3)) * 2;
    uint32_t aAh = (uint32_t)__cvta_generic_to_shared(Ah) + offA;
    uint32_t aAl = (uint32_t)__cvta_generic_to_shared(Al) + offA;

    // B x4 fetches 2 n8-tiles
    uint32_t aBh[NT / 2], aBl[NT / 2];
    #pragma unroll
    for (int p = 0; p < NT / 2; p++) {
        int n = ncol + p * 16 + (lane & 7) + ((lane >> 4) << 3);
        uint32_t offB = (n * AS + (((lane >> 3) & 1) << 3)) * 2;
        aBh[p] = (uint32_t)__cvta_generic_to_shared(Bh) + offB;
        aBl[p] = (uint32_t)__cvta_generic_to_shared(Bl) + offB;
    }

    float acc[NT][4];
    #pragma unroll
    for (int t = 0; t < NT; t++)
        #pragma unroll
        for (int j = 0; j < 4; j++) acc[t][j] = 0.f;

    #pragma unroll
    for (int kk = 0; kk < 8; kk++) {
        uint32_t kb = kk * 32;  // 16 bf16 = 32 bytes
        uint32_t ah[4], al[4];
        ldsm4(ah, aAh + kb);
        ldsm4(al, aAl + kb);
        #pragma unroll
        for (int p = 0; p < NT / 2; p++) {
            uint32_t bh[4], bl[4];
            ldsm4(bh, aBh[p] + kb);
            ldsm4(bl, aBl[p] + kb);
            mma16816(acc[2 * p],     ah, bh);
            mma16816(acc[2 * p + 1], ah, bh + 2);
            mma16816(acc[2 * p],     ah, bl);
            mma16816(acc[2 * p + 1], ah, bl + 2);
            mma16816(acc[2 * p],     al, bh);
            mma16816(acc[2 * p + 1], al, bh + 2);
        }
    }

    // epilogue: c-frag lane mapping -> direct global stores
    int r0 = rb + mrow + (lane >> 2);
    int r1 = r0 + 8;
    int cbase = cb + ncol + (lane & 3) * 2;
    #pragma unroll
    for (int t = 0; t < NT; t++) {
        int c = cbase + t * 8;
        if (r0 < N_NODES)
            *(float2*)(H + (size_t)r0 * NBTOT + c) = make_float2(acc[t][0], acc[t][1]);
        if (r1 < N_NODES)
            *(float2*)(H + (size_t)r1 * NBTOT + c) = make_float2(acc[t][2], acc[t][3]);
    }
}

// ---------------- aggregation ----------------
template <int F>
__global__ void k_agg(const float* __restrict__ H, const float* __restrict__ bias,
                      float* __restrict__ OUT) {
    constexpr int CPT = F / 32;
    int gw = (blockIdx.x * blockDim.x + threadIdx.x) >> 5;
    if (gw >= N_NODES) return;
    int lane = threadIdx.x & 31;
    float dn = g_dinv[gw];
    float acc[CPT];
    {
        float sw = dn * dn;
        if constexpr (CPT == 4) {
            float4 v = ((const float4*)(H + (size_t)gw * F))[lane];
            acc[0] = v.x * sw; acc[1] = v.y * sw; acc[2] = v.z * sw; acc[3] = v.w * sw;
        } else {
            float2 v = ((const float2*)(H + (size_t)gw * F))[lane];
            acc[0] = v.x * sw; acc[1] = v.y * sw;
        }
    }
    int b0 = g_rowptr[gw], b1 = g_rowptr[gw + 1];
    int i = b0;
    for (; i + 1 < b1; i += 2) {
        int s0 = g_csr[i], s1 = g_csr[i + 1];
        float w0 = g_dinv[s0] * dn, w1 = g_dinv[s1] * dn;
        if constexpr (CPT == 4) {
            float4 v0 = ((const float4*)(H + (size_t)s0 * F))[lane];
            float4 v1 = ((const float4*)(H + (size_t)s1 * F))[lane];
            acc[0] = fmaf(v0.x, w0, acc[0]); acc[1] = fmaf(v0.y, w0, acc[1]);
            acc[2] = fmaf(v0.z, w0, acc[2]); acc[3] = fmaf(v0.w, w0, acc[3]);
            acc[0] = fmaf(v1.x, w1, acc[0]); acc[1] = fmaf(v1.y, w1, acc[1]);
            acc[2] = fmaf(v1.z, w1, acc[2]); acc[3] = fmaf(v1.w, w1, acc[3]);
        } else {
            float2 v0 = ((const float2*)(H + (size_t)s0 * F))[lane];
            float2 v1 = ((const float2*)(H + (size_t)s1 * F))[lane];
            acc[0] = fmaf(v0.x, w0, acc[0]); acc[1] = fmaf(v0.y, w0, acc[1]);
            acc[0] = fmaf(v1.x, w1, acc[0]); acc[1] = fmaf(v1.y, w1, acc[1]);
        }
    }
    if (i < b1) {
        int s = g_csr[i];
        float wgt = g_dinv[s] * dn;
        if constexpr (CPT == 4) {
            float4 v = ((const float4*)(H + (size_t)s * F))[lane];
            acc[0] = fmaf(v.x, wgt, acc[0]); acc[1] = fmaf(v.y, wgt, acc[1]);
            acc[2] = fmaf(v.z, wgt, acc[2]); acc[3] = fmaf(v.w, wgt, acc[3]);
        } else {
            float2 v = ((const float2*)(H + (size_t)s * F))[lane];
            acc[0] = fmaf(v.x, wgt, acc[0]); acc[1] = fmaf(v.y, wgt, acc[1]);
        }
    }
    #pragma unroll
    for (int j = 0; j < CPT; j++)
        OUT[(size_t)gw * F + lane * CPT + j] = acc[j] + bias[lane * CPT + j];
}

// ---------------- batchnorm ----------------
__global__ void k_bnstats(const float* __restrict__ A, int layer) {
    int f = threadIdx.x & 127;
    int half = threadIdx.x >> 7;
    int r0 = blockIdx.x * 256;
    int r1 = min(r0 + 256, N_NODES);
    float s = 0.f, q = 0.f;
    for (int r = r0 + half; r < r1; r += 2) {
        float v = A[(size_t)r * 128 + f];
        s += v;
        q = fmaf(v, v, q);
    }
    atomicAdd(&g_bnsum[layer][f], s);
    atomicAdd(&g_bnsq[layer][f], q);
}

__global__ void k_bnfin(const float* __restrict__ gamma, const float* __restrict__ beta,
                        int layer) {
    int f = threadIdx.x;
    float mu = g_bnsum[layer][f] * (1.0f / N_NODES);
    float var = fmaxf(g_bnsq[layer][f] * (1.0f / N_NODES) - mu * mu, 0.f);
    float sc = gamma[f] * rsqrtf(var + BN_EPS);
    g_scale[f] = sc;
    g_shift[f] = beta[f] - mu * sc;
}

// ---------------- launcher ----------------
extern "C" void kernel_launch(void* const* d_in, const int* in_sizes, int n_in,
                              void* d_out, int out_size) {
    const float* x   = (const float*)d_in[0];
    const int*   ei  = (const int*)d_in[1];
    const int*   src = ei;
    const int*   dst = ei + N_EDGES;
    const float* W1 = (const float*)d_in[2];
    const float* b1 = (const float*)d_in[3];
    const float* W2 = (const float*)d_in[4];
    const float* b2 = (const float*)d_in[5];
    const float* W3 = (const float*)d_in[6];
    const float* b3 = (const float*)d_in[7];
    const float* W4 = (const float*)d_in[8];
    const float* b4 = (const float*)d_in[9];
    const float* g1 = (const float*)d_in[10];
    const float* be1 = (const float*)d_in[11];
    const float* g2 = (const float*)d_in[12];
    const float* be2 = (const float*)d_in[13];
    const float* g3 = (const float*)d_in[14];
    const float* be3 = (const float*)d_in[15];
    float* out = (float*)d_out;

    // resolve true device addresses (host shadow symbols route via ATS/C2C!)
    void* p;
    cudaGetSymbolAddress(&p, g_h);    float* d_h   = (float*)p;
    cudaGetSymbolAddress(&p, g_agg);  float* d_agg = (float*)p;
    cudaGetSymbolAddress(&p, g_whi);  __nv_bfloat16* whi = (__nv_bfloat16*)p;
    cudaGetSymbolAddress(&p, g_wlo);  __nv_bfloat16* wlo = (__nv_bfloat16*)p;

    const int smemG = (2 * 128 * 136 + 2 * 64 * 136) * 2;  // 104448
    cudaFuncSetAttribute(k_mma_gemm<128>, cudaFuncAttributeMaxDynamicSharedMemorySize, smemG);
    cudaFuncSetAttribute(k_mma_gemm<64>,  cudaFuncAttributeMaxDynamicSharedMemorySize, smemG);

    const dim3 gblk128((N_NODES + 127) / 128, 2);   // 391 x 2
    const dim3 gblk64((N_NODES + 127) / 128, 1);    // 391 x 1
    const int ablk = (N_NODES + 7) / 8;             // 6250

    // fused prep (weight split x4 + cnt zero + BN slot zero) and CSR build
    k_prep<<<148, 256>>>(W1, W2, W3, W4);
    k_count<<<(N_EDGES + 255) / 256, 256>>>(dst);
    k_scan<<<1, 1024>>>();
    k_mma_gemm<128><<<gblk128, 512, smemG>>>(x, whi + 0, wlo + 0, d_h, 0);
    k_scatter<<<(N_EDGES + 255) / 256, 256>>>(src, dst);

    // layer 1
    k_agg<128><<<ablk, 256>>>(d_h, b1, d_agg);
    k_bnstats<<<(N_NODES + 255) / 256, 256>>>(d_agg, 0);
    k_bnfin<<<1, 128>>>(g1, be1, 0);

    // layer 2 (BN+ReLU fused into GEMM A-stage)
    k_mma_gemm<128><<<gblk128, 512, smemG>>>(d_agg, whi + 16384, wlo + 16384, d_h, 1);
    k_agg<128><<<ablk, 256>>>(d_h, b2, d_agg);
    k_bnstats<<<(N_NODES + 255) / 256, 256>>>(d_agg, 1);
    k_bnfin<<<1, 128>>>(g2, be2, 1);

    // layer 3
    k_mma_gemm<128><<<gblk128, 512, smemG>>>(d_agg, whi + 32768, wlo + 32768, d_h, 1);
    k_agg<128><<<ablk, 256>>>(d_h, b3, d_agg);
    k_bnstats<<<(N_NODES + 255) / 256, 256>>>(d_agg, 2);
    k_bnfin<<<1, 128>>>(g3, be3, 2);

    // layer 4 (OUT=64)
    k_mma_gemm<64><<<gblk64, 512, smemG>>>(d_agg, whi + 49152, wlo + 49152, d_h, 1);
    k_agg<64><<<ablk, 256>>>(d_h, b4, out);
}

// round 10
// speedup vs baseline: 1.0214x; 1.0214x over previous
#include <cuda_runtime.h>
#include <cuda_bf16.h>
#include <cuda_fp16.h>
#include <cstdint>

#define N_NODES 50000
#define N_EDGES 800000
#define BN_EPS 1e-5f

// ---------------- device scratch (no allocations allowed) ----------------
__device__ __half g_h[(size_t)N_NODES * 128];   // GEMM output (fp16 -> half gather traffic)
__device__ float g_agg[(size_t)N_NODES * 128];  // aggregation output (fp32)
__device__ float g_dinv[N_NODES];
__device__ int   g_rowptr[N_NODES + 1];
__device__ int   g_cursor[N_NODES];
__device__ int   g_csr[N_EDGES];
__device__ int   g_cnt[N_NODES];
__device__ float g_bnsum[3][128];
__device__ float g_bnsq[3][128];
// bf16 split weights, transposed to B[n][k] row-major (k contiguous, K=128).
__device__ __nv_bfloat16 g_whi[57344];
__device__ __nv_bfloat16 g_wlo[57344];

// ---------------- helpers ----------------
__device__ __forceinline__ uint32_t packbf(float a, float b) {
    __nv_bfloat162 t = __floats2bfloat162_rn(a, b);
    return *(uint32_t*)&t;
}

__device__ __forceinline__ void ldsm4(uint32_t* r, uint32_t addr) {
    asm volatile("ldmatrix.sync.aligned.m8n8.x4.shared.b16 {%0,%1,%2,%3}, [%4];"
                 : "=r"(r[0]), "=r"(r[1]), "=r"(r[2]), "=r"(r[3]) : "r"(addr));
}

__device__ __forceinline__ void mma16816(float* c, const uint32_t* a, const uint32_t* b) {
    asm volatile(
        "mma.sync.aligned.m16n8k16.row.col.f32.bf16.bf16.f32 "
        "{%0,%1,%2,%3}, {%4,%5,%6,%7}, {%8,%9}, {%0,%1,%2,%3};"
        : "+f"(c[0]), "+f"(c[1]), "+f"(c[2]), "+f"(c[3])
        : "r"(a[0]), "r"(a[1]), "r"(a[2]), "r"(a[3]), "r"(b[0]), "r"(b[1]));
}

__device__ __forceinline__ void wsplit(const float* W, __nv_bfloat16* hi,
                                       __nv_bfloat16* lo, int NB, int idx) {
    int k = idx / NB, n = idx % NB;
    float v = W[idx];
    __nv_bfloat16 h = __float2bfloat16(v);
    __nv_bfloat16 l = __float2bfloat16(v - __bfloat162float(h));
    hi[n * 128 + k] = h;
    lo[n * 128 + k] = l;
}

// ---------------- fused prep: weight split x4, cnt zero, BN slot zero ----------------
__global__ void k_prep(const float* __restrict__ W1, const float* __restrict__ W2,
                       const float* __restrict__ W3, const float* __restrict__ W4) {
    int g = blockIdx.x * blockDim.x + threadIdx.x;
    int stride = gridDim.x * blockDim.x;
    for (int i = g; i < N_NODES; i += stride) g_cnt[i] = 0;
    for (int i = g; i < 3 * 128; i += stride) {
        g_bnsum[i >> 7][i & 127] = 0.f;
        g_bnsq[i >> 7][i & 127] = 0.f;
    }
    for (int i = g; i < 16384; i += stride) wsplit(W1, g_whi + 0,     g_wlo + 0,     128, i);
    for (int i = g; i < 16384; i += stride) wsplit(W2, g_whi + 16384, g_wlo + 16384, 128, i);
    for (int i = g; i < 16384; i += stride) wsplit(W3, g_whi + 32768, g_wlo + 32768, 128, i);
    for (int i = g; i < 8192;  i += stride) wsplit(W4, g_whi + 49152, g_wlo + 49152, 64,  i);
}

// ---------------- graph preprocessing ----------------
__global__ void k_count(const int* __restrict__ dst) {
    int e = blockIdx.x * blockDim.x + threadIdx.x;
    if (e < N_EDGES) atomicAdd(&g_cnt[dst[e]], 1);
}

__global__ void k_scan() {
    const int T = 1024;
    const int CH = (N_NODES + T - 1) / T;
    int t = threadIdx.x;
    int s = t * CH;
    int e = min(s + CH, N_NODES);
    int local = 0;
    for (int i = s; i < e; i++) local += g_cnt[i];

    int lane = t & 31, wid = t >> 5;
    int v = local;
    #pragma unroll
    for (int o = 1; o < 32; o <<= 1) {
        int u = __shfl_up_sync(0xFFFFFFFFu, v, o);
        if (lane >= o) v += u;
    }
    __shared__ int wsum[32];
    if (lane == 31) wsum[wid] = v;
    __syncthreads();
    if (wid == 0) {
        int wv = wsum[lane];
        #pragma unroll
        for (int o = 1; o < 32; o <<= 1) {
            int u = __shfl_up_sync(0xFFFFFFFFu, wv, o);
            if (lane >= o) wv += u;
        }
        wsum[lane] = wv;
    }
    __syncthreads();
    int incl = v + (wid > 0 ? wsum[wid - 1] : 0);
    int run = incl - local;

    for (int i = s; i < e; i++) {
        int c = g_cnt[i];
        g_rowptr[i] = run;
        g_cursor[i] = run;
        g_dinv[i]   = rsqrtf((float)c + 1.0f);
        run += c;
    }
    if (t == T - 1) g_rowptr[N_NODES] = run;
}

__global__ void k_scatter(const int* __restrict__ src, const int* __restrict__ dst) {
    int e = blockIdx.x * blockDim.x + threadIdx.x;
    if (e < N_EDGES) {
        int d = dst[e];
        int p = atomicAdd(&g_cursor[d], 1);
        g_csr[p] = src[e];
    }
}

// ---------------- HMMA GEMM: H[N,NBTOT](fp16) = act(X[N,128]) @ W[128,NBTOT] ----------------
// Double-bf16: D = Ahi*Bhi + Ahi*Blo + Alo*Bhi, fp32 accumulators.
// BN finalize fused: if layer>=0, scale/shift computed per-CTA from g_bnsum[layer].
// CTA tile: 128 rows x 64 cols (blockIdx.y = col tile). 512 threads, 16 warps.
template <int NBTOT>
__global__ void __launch_bounds__(512) k_mma_gemm(
    const float* __restrict__ X,
    const __nv_bfloat16* __restrict__ Bhi_g,
    const __nv_bfloat16* __restrict__ Blo_g,
    __half* __restrict__ H,
    const float* __restrict__ gamma, const float* __restrict__ beta, int layer) {
    constexpr int AS = 136;   // smem row stride (bf16) -> conflict-free ldmatrix
    constexpr int NT = 4;     // n8-tiles per warp (32 cols / 8)

    extern __shared__ __nv_bfloat16 sm[];
    __nv_bfloat16* Ah = sm;                    // 128*AS
    __nv_bfloat16* Al = Ah + 128 * AS;         // 128*AS
    __nv_bfloat16* Bh = Al + 128 * AS;         // 64*AS
    __nv_bfloat16* Bl = Bh + 64 * AS;          // 64*AS
    __shared__ float ss[128], sh[128];

    int tid = threadIdx.x, lane = tid & 31, w = tid >> 5;
    int rb = blockIdx.x * 128;
    int cb = blockIdx.y * 64;

    // fused BN finalize: per-CTA scale/shift from accumulated stats
    if (layer >= 0) {
        if (tid < 128) {
            float mu = g_bnsum[layer][tid] * (1.0f / N_NODES);
            float var = fmaxf(g_bnsq[layer][tid] * (1.0f / N_NODES) - mu * mu, 0.f);
            float sc = gamma[tid] * rsqrtf(var + BN_EPS);
            ss[tid] = sc;
            sh[tid] = beta[tid] - mu * sc;
        }
        __syncthreads();
    }

    // stage B slice [cb, cb+64) (pre-split bf16, [n][k] k-contiguous), 16B chunks
    for (int c = tid; c < 64 * 16; c += 512) {
        int n = c >> 4, s = c & 15;
        *(uint4*)(Bh + n * AS + s * 8) = ((const uint4*)Bhi_g)[(cb + n) * 16 + s];
        *(uint4*)(Bl + n * AS + s * 8) = ((const uint4*)Blo_g)[(cb + n) * 16 + s];
    }

    // stage A: load fp32, optional BN+ReLU, split into hi/lo bf16
    #pragma unroll
    for (int i = 0; i < 8; i++) {
        int idx = tid + i * 512;         // 0..4095
        int row = idx >> 5, q = idx & 31;
        int r = rb + row;
        float4 v = make_float4(0.f, 0.f, 0.f, 0.f);
        if (r < N_NODES) {
            v = ((const float4*)X)[(size_t)r * 32 + q];
            if (layer >= 0) {
                int k = q * 4;
                v.x = fmaxf(fmaf(v.x, ss[k + 0], sh[k + 0]), 0.f);
                v.y = fmaxf(fmaf(v.y, ss[k + 1], sh[k + 1]), 0.f);
                v.z = fmaxf(fmaf(v.z, ss[k + 2], sh[k + 2]), 0.f);
                v.w = fmaxf(fmaf(v.w, ss[k + 3], sh[k + 3]), 0.f);
            }
        }
        float hx = __bfloat162float(__float2bfloat16(v.x));
        float hy = __bfloat162float(__float2bfloat16(v.y));
        float hz = __bfloat162float(__float2bfloat16(v.z));
        float hw = __bfloat162float(__float2bfloat16(v.w));
        uint32_t h01 = packbf(v.x, v.y), h23 = packbf(v.z, v.w);
        uint32_t l01 = packbf(v.x - hx, v.y - hy), l23 = packbf(v.z - hz, v.w - hw);
        *(uint2*)(Ah + row * AS + q * 4) = make_uint2(h01, h23);
        *(uint2*)(Al + row * AS + q * 4) = make_uint2(l01, l23);
    }
    __syncthreads();

    int mrow = (w & 7) * 16;
    int ncol = (w >> 3) * 32;   // local col offset within the 64-col slice

    uint32_t offA = ((mrow + (lane & 15)) * AS + ((lane >> 4) << 3)) * 2;
    uint32_t aAh = (uint32_t)__cvta_generic_to_shared(Ah) + offA;
    uint32_t aAl = (uint32_t)__cvta_generic_to_shared(Al) + offA;

    uint32_t aBh[NT / 2], aBl[NT / 2];
    #pragma unroll
    for (int p = 0; p < NT / 2; p++) {
        int n = ncol + p * 16 + (lane & 7) + ((lane >> 4) << 3);
        uint32_t offB = (n * AS + (((lane >> 3) & 1) << 3)) * 2;
        aBh[p] = (uint32_t)__cvta_generic_to_shared(Bh) + offB;
        aBl[p] = (uint32_t)__cvta_generic_to_shared(Bl) + offB;
    }

    float acc[NT][4];
    #pragma unroll
    for (int t = 0; t < NT; t++)
        #pragma unroll
        for (int j = 0; j < 4; j++) acc[t][j] = 0.f;

    #pragma unroll
    for (int kk = 0; kk < 8; kk++) {
        uint32_t kb = kk * 32;  // 16 bf16 = 32 bytes
        uint32_t ah[4], al[4];
        ldsm4(ah, aAh + kb);
        ldsm4(al, aAl + kb);
        #pragma unroll
        for (int p = 0; p < NT / 2; p++) {
            uint32_t bh[4], bl[4];
            ldsm4(bh, aBh[p] + kb);
            ldsm4(bl, aBl[p] + kb);
            mma16816(acc[2 * p],     ah, bh);
            mma16816(acc[2 * p + 1], ah, bh + 2);
            mma16816(acc[2 * p],     ah, bl);
            mma16816(acc[2 * p + 1], ah, bl + 2);
            mma16816(acc[2 * p],     al, bh);
            mma16816(acc[2 * p + 1], al, bh + 2);
        }
    }

    // epilogue: fp16 stores
    int r0 = rb + mrow + (lane >> 2);
    int r1 = r0 + 8;
    int cbase = cb + ncol + (lane & 3) * 2;
    #pragma unroll
    for (int t = 0; t < NT; t++) {
        int c = cbase + t * 8;
        if (r0 < N_NODES)
            *(__half2*)(H + (size_t)r0 * NBTOT + c) = __floats2half2_rn(acc[t][0], acc[t][1]);
        if (r1 < N_NODES)
            *(__half2*)(H + (size_t)r1 * NBTOT + c) = __floats2half2_rn(acc[t][2], acc[t][3]);
    }
}

// ---------------- aggregation (fp16 gather) + fused BN stats ----------------
// warp per node; lane handles CPT consecutive feature cols.
template <int F, int DOBN>
__global__ void __launch_bounds__(256) k_agg(
    const __half* __restrict__ H, const float* __restrict__ bias,
    float* __restrict__ OUT, int layer) {
    constexpr int CPT = F / 32;
    __shared__ float sS[F], sQ[F];
    int tid = threadIdx.x, lane = tid & 31;
    if (DOBN) {
        if (tid < F) { sS[tid] = 0.f; sQ[tid] = 0.f; }
        __syncthreads();
    }
    int gw = (blockIdx.x * blockDim.x + tid) >> 5;
    float o[CPT];
    #pragma unroll
    for (int j = 0; j < CPT; j++) o[j] = 0.f;
    bool valid = gw < N_NODES;
    if (valid) {
        float dn = g_dinv[gw];
        float acc[CPT];
        {
            float sw = dn * dn;
            if constexpr (CPT == 4) {
                uint2 u = ((const uint2*)(H + (size_t)gw * F))[lane];
                float2 f0 = __half22float2(*(__half2*)&u.x);
                float2 f1 = __half22float2(*(__half2*)&u.y);
                acc[0] = f0.x * sw; acc[1] = f0.y * sw;
                acc[2] = f1.x * sw; acc[3] = f1.y * sw;
            } else {
                __half2 hv = ((const __half2*)(H + (size_t)gw * F))[lane];
                float2 f = __half22float2(hv);
                acc[0] = f.x * sw; acc[1] = f.y * sw;
            }
        }
        int b0 = g_rowptr[gw], b1 = g_rowptr[gw + 1];
        int i = b0;
        for (; i + 1 < b1; i += 2) {
            int s0 = g_csr[i], s1 = g_csr[i + 1];
            float w0 = g_dinv[s0] * dn, w1 = g_dinv[s1] * dn;
            if constexpr (CPT == 4) {
                uint2 u0 = ((const uint2*)(H + (size_t)s0 * F))[lane];
                uint2 u1 = ((const uint2*)(H + (size_t)s1 * F))[lane];
                float2 a0 = __half22float2(*(__half2*)&u0.x);
                float2 a1 = __half22float2(*(__half2*)&u0.y);
                float2 c0 = __half22float2(*(__half2*)&u1.x);
                float2 c1 = __half22float2(*(__half2*)&u1.y);
                acc[0] = fmaf(a0.x, w0, acc[0]); acc[1] = fmaf(a0.y, w0, acc[1]);
                acc[2] = fmaf(a1.x, w0, acc[2]); acc[3] = fmaf(a1.y, w0, acc[3]);
                acc[0] = fmaf(c0.x, w1, acc[0]); acc[1] = fmaf(c0.y, w1, acc[1]);
                acc[2] = fmaf(c1.x, w1, acc[2]); acc[3] = fmaf(c1.y, w1, acc[3]);
            } else {
                float2 a = __half22float2(((const __half2*)(H + (size_t)s0 * F))[lane]);
                float2 c = __half22float2(((const __half2*)(H + (size_t)s1 * F))[lane]);
                acc[0] = fmaf(a.x, w0, acc[0]); acc[1] = fmaf(a.y, w0, acc[1]);
                acc[0] = fmaf(c.x, w1, acc[0]); acc[1] = fmaf(c.y, w1, acc[1]);
            }
        }
        if (i < b1) {
            int s = g_csr[i];
            float wgt = g_dinv[s] * dn;
            if constexpr (CPT == 4) {
                uint2 u = ((const uint2*)(H + (size_t)s * F))[lane];
                float2 a0 = __half22float2(*(__half2*)&u.x);
                float2 a1 = __half22float2(*(__half2*)&u.y);
                acc[0] = fmaf(a0.x, wgt, acc[0]); acc[1] = fmaf(a0.y, wgt, acc[1]);
                acc[2] = fmaf(a1.x, wgt, acc[2]); acc[3] = fmaf(a1.y, wgt, acc[3]);
            } else {
                float2 a = __half22float2(((const __half2*)(H + (size_t)s * F))[lane]);
                acc[0] = fmaf(a.x, wgt, acc[0]); acc[1] = fmaf(a.y, wgt, acc[1]);
            }
        }
        #pragma unroll
        for (int j = 0; j < CPT; j++) {
            o[j] = acc[j] + bias[lane * CPT + j];
            OUT[(size_t)gw * F + lane * CPT + j] = o[j];
        }
    }
    if (DOBN) {
        #pragma unroll
        for (int j = 0; j < CPT; j++) {
            atomicAdd(&sS[lane * CPT + j], o[j]);
            atomicAdd(&sQ[lane * CPT + j], o[j] * o[j]);
        }
        __syncthreads();
        if (tid < F) {
            atomicAdd(&g_bnsum[layer][tid], sS[tid]);
            atomicAdd(&g_bnsq[layer][tid], sQ[tid]);
        }
    }
}

// ---------------- launcher ----------------
extern "C" void kernel_launch(void* const* d_in, const int* in_sizes, int n_in,
                              void* d_out, int out_size) {
    const float* x   = (const float*)d_in[0];
    const int*   ei  = (const int*)d_in[1];
    const int*   src = ei;
    const int*   dst = ei + N_EDGES;
    const float* W1 = (const float*)d_in[2];
    const float* b1 = (const float*)d_in[3];
    const float* W2 = (const float*)d_in[4];
    const float* b2 = (const float*)d_in[5];
    const float* W3 = (const float*)d_in[6];
    const float* b3 = (const float*)d_in[7];
    const float* W4 = (const float*)d_in[8];
    const float* b4 = (const float*)d_in[9];
    const float* g1 = (const float*)d_in[10];
    const float* be1 = (const float*)d_in[11];
    const float* g2 = (const float*)d_in[12];
    const float* be2 = (const float*)d_in[13];
    const float* g3 = (const float*)d_in[14];
    const float* be3 = (const float*)d_in[15];
    float* out = (float*)d_out;

    // resolve true device addresses (host shadow symbols route via ATS/C2C!)
    void* p;
    cudaGetSymbolAddress(&p, g_h);    __half* d_h  = (__half*)p;
    cudaGetSymbolAddress(&p, g_agg);  float* d_agg = (float*)p;
    cudaGetSymbolAddress(&p, g_whi);  __nv_bfloat16* whi = (__nv_bfloat16*)p;
    cudaGetSymbolAddress(&p, g_wlo);  __nv_bfloat16* wlo = (__nv_bfloat16*)p;

    const int smemG = (2 * 128 * 136 + 2 * 64 * 136) * 2;  // 104448
    cudaFuncSetAttribute(k_mma_gemm<128>, cudaFuncAttributeMaxDynamicSharedMemorySize, smemG);
    cudaFuncSetAttribute(k_mma_gemm<64>,  cudaFuncAttributeMaxDynamicSharedMemorySize, smemG);

    const dim3 gblk128((N_NODES + 127) / 128, 2);   // 391 x 2
    const dim3 gblk64((N_NODES + 127) / 128, 1);    // 391 x 1
    const int ablk = (N_NODES + 7) / 8;             // 6250 warps-per-node blocks

    // prep + CSR build; layer-1 GEMM interleaved (independent of CSR)
    k_prep<<<148, 256>>>(W1, W2, W3, W4);
    k_count<<<(N_EDGES + 255) / 256, 256>>>(dst);
    k_scan<<<1, 1024>>>();
    k_mma_gemm<128><<<gblk128, 512, smemG>>>(x, whi + 0, wlo + 0, d_h, g1, be1, -1);
    k_scatter<<<(N_EDGES + 255) / 256, 256>>>(src, dst);

    // layer 1: agg + fused BN stats(0)
    k_agg<128, 1><<<ablk, 256>>>(d_h, b1, d_agg, 0);
    // layer 2: GEMM (BN finalize(0) + ReLU fused), agg + BN stats(1)
    k_mma_gemm<128><<<gblk128, 512, smemG>>>(d_agg, whi + 16384, wlo + 16384, d_h, g1, be1, 0);
    k_agg<128, 1><<<ablk, 256>>>(d_h, b2, d_agg, 1);
    // layer 3
    k_mma_gemm<128><<<gblk128, 512, smemG>>>(d_agg, whi + 32768, wlo + 32768, d_h, g2, be2, 1);
    k_agg<128, 1><<<ablk, 256>>>(d_h, b3, d_agg, 2);
    // layer 4 (OUT=64), final agg writes d_out, no BN
    k_mma_gemm<64><<<gblk64, 512, smemG>>>(d_agg, whi + 49152, wlo + 49152, d_h, g3, be3, 2);
    k_agg<64, 0><<<ablk, 256>>>(d_h, b4, out, 0);
}

// round 11
// speedup vs baseline: 1.0613x; 1.0391x over previous
#include <cuda_runtime.h>
#include <cuda_bf16.h>
#include <cuda_fp16.h>
#include <cstdint>

#define N_NODES 50000
#define N_EDGES 800000
#define BN_EPS 1e-5f

// ---------------- device scratch (no allocations allowed) ----------------
__device__ __half g_h[(size_t)N_NODES * 128];   // GEMM output (fp16 gather operand)
__device__ float g_agg[(size_t)N_NODES * 128];  // aggregation output (fp32)
__device__ float g_dinv[N_NODES];
__device__ int   g_rowptr[N_NODES + 1];
__device__ int   g_cursor[N_NODES];
__device__ int   g_csr[N_EDGES];
__device__ float g_wt[N_EDGES];                 // precomputed dinv[src]*dinv[dst]
__device__ int   g_cnt[N_NODES];
__device__ float g_bnsum[3][8][128];            // 8 slots to cut atomic chains
__device__ float g_bnsq[3][8][128];
// bf16 split weights, transposed to B[n][k] row-major (k contiguous, K=128).
__device__ __nv_bfloat16 g_whi[57344];
__device__ __nv_bfloat16 g_wlo[57344];

// ---------------- helpers ----------------
__device__ __forceinline__ uint32_t packbf(float a, float b) {
    __nv_bfloat162 t = __floats2bfloat162_rn(a, b);
    return *(uint32_t*)&t;
}

__device__ __forceinline__ void ldsm4(uint32_t* r, uint32_t addr) {
    asm volatile("ldmatrix.sync.aligned.m8n8.x4.shared.b16 {%0,%1,%2,%3}, [%4];"
                 : "=r"(r[0]), "=r"(r[1]), "=r"(r[2]), "=r"(r[3]) : "r"(addr));
}

__device__ __forceinline__ void mma16816(float* c, const uint32_t* a, const uint32_t* b) {
    asm volatile(
        "mma.sync.aligned.m16n8k16.row.col.f32.bf16.bf16.f32 "
        "{%0,%1,%2,%3}, {%4,%5,%6,%7}, {%8,%9}, {%0,%1,%2,%3};"
        : "+f"(c[0]), "+f"(c[1]), "+f"(c[2]), "+f"(c[3])
        : "r"(a[0]), "r"(a[1]), "r"(a[2]), "r"(a[3]), "r"(b[0]), "r"(b[1]));
}

__device__ __forceinline__ void wsplit(const float* W, __nv_bfloat16* hi,
                                       __nv_bfloat16* lo, int NB, int idx) {
    int k = idx / NB, n = idx % NB;
    float v = W[idx];
    __nv_bfloat16 h = __float2bfloat16(v);
    __nv_bfloat16 l = __float2bfloat16(v - __bfloat162float(h));
    hi[n * 128 + k] = h;
    lo[n * 128 + k] = l;
}

// ---------------- fused prep ----------------
__global__ void k_prep(const float* __restrict__ W1, const float* __restrict__ W2,
                       const float* __restrict__ W3, const float* __restrict__ W4) {
    int g = blockIdx.x * blockDim.x + threadIdx.x;
    int stride = gridDim.x * blockDim.x;
    for (int i = g; i < N_NODES; i += stride) g_cnt[i] = 0;
    for (int i = g; i < 3 * 8 * 128; i += stride) {
        ((float*)g_bnsum)[i] = 0.f;
        ((float*)g_bnsq)[i] = 0.f;
    }
    for (int i = g; i < 16384; i += stride) wsplit(W1, g_whi + 0,     g_wlo + 0,     128, i);
    for (int i = g; i < 16384; i += stride) wsplit(W2, g_whi + 16384, g_wlo + 16384, 128, i);
    for (int i = g; i < 16384; i += stride) wsplit(W3, g_whi + 32768, g_wlo + 32768, 128, i);
    for (int i = g; i < 8192;  i += stride) wsplit(W4, g_whi + 49152, g_wlo + 49152, 64,  i);
}

// ---------------- graph preprocessing ----------------
__global__ void k_count(const int* __restrict__ dst) {
    int e = blockIdx.x * blockDim.x + threadIdx.x;
    if (e < N_EDGES) atomicAdd(&g_cnt[dst[e]], 1);
}

__global__ void k_scan() {
    const int T = 1024;
    const int CH = (N_NODES + T - 1) / T;
    int t = threadIdx.x;
    int s = t * CH;
    int e = min(s + CH, N_NODES);
    int local = 0;
    for (int i = s; i < e; i++) local += g_cnt[i];

    int lane = t & 31, wid = t >> 5;
    int v = local;
    #pragma unroll
    for (int o = 1; o < 32; o <<= 1) {
        int u = __shfl_up_sync(0xFFFFFFFFu, v, o);
        if (lane >= o) v += u;
    }
    __shared__ int wsum[32];
    if (lane == 31) wsum[wid] = v;
    __syncthreads();
    if (wid == 0) {
        int wv = wsum[lane];
        #pragma unroll
        for (int o = 1; o < 32; o <<= 1) {
            int u = __shfl_up_sync(0xFFFFFFFFu, wv, o);
            if (lane >= o) wv += u;
        }
        wsum[lane] = wv;
    }
    __syncthreads();
    int incl = v + (wid > 0 ? wsum[wid - 1] : 0);
    int run = incl - local;

    for (int i = s; i < e; i++) {
        int c = g_cnt[i];
        g_rowptr[i] = run;
        g_cursor[i] = run;
        g_dinv[i]   = rsqrtf((float)c + 1.0f);
        run += c;
    }
    if (t == T - 1) g_rowptr[N_NODES] = run;
}

// scatter with precomputed edge weight: removes dinv loads from agg's chain
__global__ void k_scatter(const int* __restrict__ src, const int* __restrict__ dst) {
    int e = blockIdx.x * blockDim.x + threadIdx.x;
    if (e < N_EDGES) {
        int s = src[e], d = dst[e];
        int p = atomicAdd(&g_cursor[d], 1);
        g_csr[p] = s;
        g_wt[p] = g_dinv[s] * g_dinv[d];
    }
}

// ---------------- HMMA GEMM: H[N,NBTOT](fp16) = act(X[N,128]) @ W[128,NBTOT] ----------------
template <int NBTOT>
__global__ void __launch_bounds__(512) k_mma_gemm(
    const float* __restrict__ X,
    const __nv_bfloat16* __restrict__ Bhi_g,
    const __nv_bfloat16* __restrict__ Blo_g,
    __half* __restrict__ H,
    const float* __restrict__ gamma, const float* __restrict__ beta, int layer) {
    constexpr int AS = 136;
    constexpr int NT = 4;

    extern __shared__ __nv_bfloat16 sm[];
    __nv_bfloat16* Ah = sm;
    __nv_bfloat16* Al = Ah + 128 * AS;
    __nv_bfloat16* Bh = Al + 128 * AS;
    __nv_bfloat16* Bl = Bh + 64 * AS;
    __shared__ float ss[128], sh[128];

    int tid = threadIdx.x, lane = tid & 31, w = tid >> 5;
    int rb = blockIdx.x * 128;
    int cb = blockIdx.y * 64;

    // fused BN finalize: sum 8 slots, compute scale/shift
    if (layer >= 0) {
        if (tid < 128) {
            float s = 0.f, q = 0.f;
            #pragma unroll
            for (int j = 0; j < 8; j++) {
                s += g_bnsum[layer][j][tid];
                q += g_bnsq[layer][j][tid];
            }
            float mu = s * (1.0f / N_NODES);
            float var = fmaxf(q * (1.0f / N_NODES) - mu * mu, 0.f);
            float sc = gamma[tid] * rsqrtf(var + BN_EPS);
            ss[tid] = sc;
            sh[tid] = beta[tid] - mu * sc;
        }
        __syncthreads();
    }

    for (int c = tid; c < 64 * 16; c += 512) {
        int n = c >> 4, s = c & 15;
        *(uint4*)(Bh + n * AS + s * 8) = ((const uint4*)Bhi_g)[(cb + n) * 16 + s];
        *(uint4*)(Bl + n * AS + s * 8) = ((const uint4*)Blo_g)[(cb + n) * 16 + s];
    }

    #pragma unroll
    for (int i = 0; i < 8; i++) {
        int idx = tid + i * 512;
        int row = idx >> 5, q = idx & 31;
        int r = rb + row;
        float4 v = make_float4(0.f, 0.f, 0.f, 0.f);
        if (r < N_NODES) {
            v = ((const float4*)X)[(size_t)r * 32 + q];
            if (layer >= 0) {
                int k = q * 4;
                v.x = fmaxf(fmaf(v.x, ss[k + 0], sh[k + 0]), 0.f);
                v.y = fmaxf(fmaf(v.y, ss[k + 1], sh[k + 1]), 0.f);
                v.z = fmaxf(fmaf(v.z, ss[k + 2], sh[k + 2]), 0.f);
                v.w = fmaxf(fmaf(v.w, ss[k + 3], sh[k + 3]), 0.f);
            }
        }
        float hx = __bfloat162float(__float2bfloat16(v.x));
        float hy = __bfloat162float(__float2bfloat16(v.y));
        float hz = __bfloat162float(__float2bfloat16(v.z));
        float hw = __bfloat162float(__float2bfloat16(v.w));
        uint32_t h01 = packbf(v.x, v.y), h23 = packbf(v.z, v.w);
        uint32_t l01 = packbf(v.x - hx, v.y - hy), l23 = packbf(v.z - hz, v.w - hw);
        *(uint2*)(Ah + row * AS + q * 4) = make_uint2(h01, h23);
        *(uint2*)(Al + row * AS + q * 4) = make_uint2(l01, l23);
    }
    __syncthreads();

    int mrow = (w & 7) * 16;
    int ncol = (w >> 3) * 32;

    uint32_t offA = ((mrow + (lane & 15)) * AS + ((lane >> 4) << 3)) * 2;
    uint32_t aAh = (uint32_t)__cvta_generic_to_shared(Ah) + offA;
    uint32_t aAl = (uint32_t)__cvta_generic_to_shared(Al) + offA;

    uint32_t aBh[NT / 2], aBl[NT / 2];
    #pragma unroll
    for (int p = 0; p < NT / 2; p++) {
        int n = ncol + p * 16 + (lane & 7) + ((lane >> 4) << 3);
        uint32_t offB = (n * AS + (((lane >> 3) & 1) << 3)) * 2;
        aBh[p] = (uint32_t)__cvta_generic_to_shared(Bh) + offB;
        aBl[p] = (uint32_t)__cvta_generic_to_shared(Bl) + offB;
    }

    float acc[NT][4];
    #pragma unroll
    for (int t = 0; t < NT; t++)
        #pragma unroll
        for (int j = 0; j < 4; j++) acc[t][j] = 0.f;

    #pragma unroll
    for (int kk = 0; kk < 8; kk++) {
        uint32_t kb = kk * 32;
        uint32_t ah[4], al[4];
        ldsm4(ah, aAh + kb);
        ldsm4(al, aAl + kb);
        #pragma unroll
        for (int p = 0; p < NT / 2; p++) {
            uint32_t bh[4], bl[4];
            ldsm4(bh, aBh[p] + kb);
            ldsm4(bl, aBl[p] + kb);
            mma16816(acc[2 * p],     ah, bh);
            mma16816(acc[2 * p + 1], ah, bh + 2);
            mma16816(acc[2 * p],     ah, bl);
            mma16816(acc[2 * p + 1], ah, bl + 2);
            mma16816(acc[2 * p],     al, bh);
            mma16816(acc[2 * p + 1], al, bh + 2);
        }
    }

    int r0 = rb + mrow + (lane >> 2);
    int r1 = r0 + 8;
    int cbase = cb + ncol + (lane & 3) * 2;
    #pragma unroll
    for (int t = 0; t < NT; t++) {
        int c = cbase + t * 8;
        if (r0 < N_NODES)
            *(__half2*)(H + (size_t)r0 * NBTOT + c) = __floats2half2_rn(acc[t][0], acc[t][1]);
        if (r1 < N_NODES)
            *(__half2*)(H + (size_t)r1 * NBTOT + c) = __floats2half2_rn(acc[t][2], acc[t][3]);
    }
}

// ---------------- aggregation: warp/node, 4-way unrolled, precomputed weights ----------------
template <int F, int DOBN>
__global__ void __launch_bounds__(256) k_agg(
    const __half* __restrict__ H, const float* __restrict__ bias,
    float* __restrict__ OUT, int layer) {
    constexpr int CPT = F / 32;
    __shared__ float sS[F], sQ[F];
    int tid = threadIdx.x, lane = tid & 31;
    if (DOBN) {
        if (tid < F) { sS[tid] = 0.f; sQ[tid] = 0.f; }
        __syncthreads();
    }
    int gw = (blockIdx.x * blockDim.x + tid) >> 5;
    float o[CPT];
    #pragma unroll
    for (int j = 0; j < CPT; j++) o[j] = 0.f;
    if (gw < N_NODES) {
        float dn = g_dinv[gw];
        float acc[CPT];
        {
            float sw = dn * dn;
            if constexpr (CPT == 4) {
                uint2 u = ((const uint2*)(H + (size_t)gw * F))[lane];
                float2 f0 = __half22float2(*(__half2*)&u.x);
                float2 f1 = __half22float2(*(__half2*)&u.y);
                acc[0] = f0.x * sw; acc[1] = f0.y * sw;
                acc[2] = f1.x * sw; acc[3] = f1.y * sw;
            } else {
                float2 f = __half22float2(((const __half2*)(H + (size_t)gw * F))[lane]);
                acc[0] = f.x * sw; acc[1] = f.y * sw;
            }
        }
        int b0 = g_rowptr[gw], b1 = g_rowptr[gw + 1];
        int i = b0;
        // 4-way unroll: batch independent index/weight loads, then independent gathers
        for (; i + 4 <= b1; i += 4) {
            int s0 = g_csr[i], s1 = g_csr[i + 1], s2 = g_csr[i + 2], s3 = g_csr[i + 3];
            float w0 = g_wt[i], w1 = g_wt[i + 1], w2 = g_wt[i + 2], w3 = g_wt[i + 3];
            if constexpr (CPT == 4) {
                uint2 u0 = ((const uint2*)(H + (size_t)s0 * F))[lane];
                uint2 u1 = ((const uint2*)(H + (size_t)s1 * F))[lane];
                uint2 u2 = ((const uint2*)(H + (size_t)s2 * F))[lane];
                uint2 u3 = ((const uint2*)(H + (size_t)s3 * F))[lane];
                float2 a, b;
                a = __half22float2(*(__half2*)&u0.x); b = __half22float2(*(__half2*)&u0.y);
                acc[0] = fmaf(a.x, w0, acc[0]); acc[1] = fmaf(a.y, w0, acc[1]);
                acc[2] = fmaf(b.x, w0, acc[2]); acc[3] = fmaf(b.y, w0, acc[3]);
                a = __half22float2(*(__half2*)&u1.x); b = __half22float2(*(__half2*)&u1.y);
                acc[0] = fmaf(a.x, w1, acc[0]); acc[1] = fmaf(a.y, w1, acc[1]);
                acc[2] = fmaf(b.x, w1, acc[2]); acc[3] = fmaf(b.y, w1, acc[3]);
                a = __half22float2(*(__half2*)&u2.x); b = __half22float2(*(__half2*)&u2.y);
                acc[0] = fmaf(a.x, w2, acc[0]); acc[1] = fmaf(a.y, w2, acc[1]);
                acc[2] = fmaf(b.x, w2, acc[2]); acc[3] = fmaf(b.y, w2, acc[3]);
                a = __half22float2(*(__half2*)&u3.x); b = __half22float2(*(__half2*)&u3.y);
                acc[0] = fmaf(a.x, w3, acc[0]); acc[1] = fmaf(a.y, w3, acc[1]);
                acc[2] = fmaf(b.x, w3, acc[2]); acc[3] = fmaf(b.y, w3, acc[3]);
            } else {
                __half2 h0 = ((const __half2*)(H + (size_t)s0 * F))[lane];
                __half2 h1 = ((const __half2*)(H + (size_t)s1 * F))[lane];
                __half2 h2 = ((const __half2*)(H + (size_t)s2 * F))[lane];
                __half2 h3 = ((const __half2*)(H + (size_t)s3 * F))[lane];
                float2 f;
                f = __half22float2(h0); acc[0] = fmaf(f.x, w0, acc[0]); acc[1] = fmaf(f.y, w0, acc[1]);
                f = __half22float2(h1); acc[0] = fmaf(f.x, w1, acc[0]); acc[1] = fmaf(f.y, w1, acc[1]);
                f = __half22float2(h2); acc[0] = fmaf(f.x, w2, acc[0]); acc[1] = fmaf(f.y, w2, acc[1]);
                f = __half22float2(h3); acc[0] = fmaf(f.x, w3, acc[0]); acc[1] = fmaf(f.y, w3, acc[1]);
            }
        }
        for (; i < b1; i++) {
            int s = g_csr[i];
            float wgt = g_wt[i];
            if constexpr (CPT == 4) {
                uint2 u = ((const uint2*)(H + (size_t)s * F))[lane];
                float2 a = __half22float2(*(__half2*)&u.x);
                float2 b = __half22float2(*(__half2*)&u.y);
                acc[0] = fmaf(a.x, wgt, acc[0]); acc[1] = fmaf(a.y, wgt, acc[1]);
                acc[2] = fmaf(b.x, wgt, acc[2]); acc[3] = fmaf(b.y, wgt, acc[3]);
            } else {
                float2 f = __half22float2(((const __half2*)(H + (size_t)s * F))[lane]);
                acc[0] = fmaf(f.x, wgt, acc[0]); acc[1] = fmaf(f.y, wgt, acc[1]);
            }
        }
        #pragma unroll
        for (int j = 0; j < CPT; j++) {
            o[j] = acc[j] + bias[lane * CPT + j];
            OUT[(size_t)gw * F + lane * CPT + j] = o[j];
        }
    }
    if (DOBN) {
        #pragma unroll
        for (int j = 0; j < CPT; j++) {
            atomicAdd(&sS[lane * CPT + j], o[j]);
            atomicAdd(&sQ[lane * CPT + j], o[j] * o[j]);
        }
        __syncthreads();
        int slot = blockIdx.x & 7;
        if (tid < F) {
            atomicAdd(&g_bnsum[layer][slot][tid], sS[tid]);
            atomicAdd(&g_bnsq[layer][slot][tid], sQ[tid]);
        }
    }
}

// ---------------- launcher ----------------
extern "C" void kernel_launch(void* const* d_in, const int* in_sizes, int n_in,
                              void* d_out, int out_size) {
    const float* x   = (const float*)d_in[0];
    const int*   ei  = (const int*)d_in[1];
    const int*   src = ei;
    const int*   dst = ei + N_EDGES;
    const float* W1 = (const float*)d_in[2];
    const float* b1 = (const float*)d_in[3];
    const float* W2 = (const float*)d_in[4];
    const float* b2 = (const float*)d_in[5];
    const float* W3 = (const float*)d_in[6];
    const float* b3 = (const float*)d_in[7];
    const float* W4 = (const float*)d_in[8];
    const float* b4 = (const float*)d_in[9];
    const float* g1 = (const float*)d_in[10];
    const float* be1 = (const float*)d_in[11];
    const float* g2 = (const float*)d_in[12];
    const float* be2 = (const float*)d_in[13];
    const float* g3 = (const float*)d_in[14];
    const float* be3 = (const float*)d_in[15];
    float* out = (float*)d_out;

    // resolve true device addresses (host shadow symbols route via ATS/C2C!)
    void* p;
    cudaGetSymbolAddress(&p, g_h);    __half* d_h  = (__half*)p;
    cudaGetSymbolAddress(&p, g_agg);  float* d_agg = (float*)p;
    cudaGetSymbolAddress(&p, g_whi);  __nv_bfloat16* whi = (__nv_bfloat16*)p;
    cudaGetSymbolAddress(&p, g_wlo);  __nv_bfloat16* wlo = (__nv_bfloat16*)p;

    const int smemG = (2 * 128 * 136 + 2 * 64 * 136) * 2;  // 104448
    cudaFuncSetAttribute(k_mma_gemm<128>, cudaFuncAttributeMaxDynamicSharedMemorySize, smemG);
    cudaFuncSetAttribute(k_mma_gemm<64>,  cudaFuncAttributeMaxDynamicSharedMemorySize, smemG);

    const dim3 gblk128((N_NODES + 127) / 128, 2);
    const dim3 gblk64((N_NODES + 127) / 128, 1);
    const int ablk = (N_NODES + 7) / 8;

    // prep + CSR build; layer-1 GEMM interleaved (independent of CSR)
    k_prep<<<148, 256>>>(W1, W2, W3, W4);
    k_count<<<(N_EDGES + 255) / 256, 256>>>(dst);
    k_scan<<<1, 1024>>>();
    k_mma_gemm<128><<<gblk128, 512, smemG>>>(x, whi + 0, wlo + 0, d_h, g1, be1, -1);
    k_scatter<<<(N_EDGES + 255) / 256, 256>>>(src, dst);

    // layer 1: agg + fused BN stats(0)
    k_agg<128, 1><<<ablk, 256>>>(d_h, b1, d_agg, 0);
    // layer 2: GEMM (BN finalize(0) + ReLU fused), agg + BN stats(1)
    k_mma_gemm<128><<<gblk128, 512, smemG>>>(d_agg, whi + 16384, wlo + 16384, d_h, g1, be1, 0);
    k_agg<128, 1><<<ablk, 256>>>(d_h, b2, d_agg, 1);
    // layer 3
    k_mma_gemm<128><<<gblk128, 512, smemG>>>(d_agg, whi + 32768, wlo + 32768, d_h, g2, be2, 1);
    k_agg<128, 1><<<ablk, 256>>>(d_h, b3, d_agg, 2);
    // layer 4 (OUT=64), final agg writes d_out, no BN
    k_mma_gemm<64><<<gblk64, 512, smemG>>>(d_agg, whi + 49152, wlo + 49152, d_h, g3, be3, 2);
    k_agg<64, 0><<<ablk, 256>>>(d_h, b4, out, 0);
}

// round 12
// speedup vs baseline: 1.5172x; 1.4295x over previous
#include <cuda_runtime.h>
#include <cuda_bf16.h>
#include <cuda_fp16.h>
#include <cstdint>

#define N_NODES 50000
#define N_EDGES 800000
#define BN_EPS 1e-5f
#define SCAN_BLOCKS 64
#define SCAN_CH 782   // ceil(50000/64)

// ---------------- device scratch (no allocations allowed) ----------------
__device__ __half g_h[(size_t)N_NODES * 128];   // GEMM output (fp16 gather operand)
__device__ float g_agg[(size_t)N_NODES * 128];  // aggregation output (fp32)
__device__ float g_dinv[N_NODES];
__device__ int   g_rowptr[N_NODES + 1];
__device__ int   g_cursor[N_NODES];
__device__ uint2 g_csrwt[N_EDGES];              // packed (src_idx, weight_bits)
__device__ int   g_cnt[N_NODES];
__device__ int   g_part[SCAN_BLOCKS];
__device__ float g_bnsum[3][8][128];            // 8 slots to cut atomic chains
__device__ float g_bnsq[3][8][128];
// bf16 split weights, transposed to B[n][k] row-major (k contiguous, K=128).
__device__ __nv_bfloat16 g_whi[57344];
__device__ __nv_bfloat16 g_wlo[57344];

// ---------------- helpers ----------------
__device__ __forceinline__ uint32_t packbf(float a, float b) {
    __nv_bfloat162 t = __floats2bfloat162_rn(a, b);
    return *(uint32_t*)&t;
}

__device__ __forceinline__ void ldsm4(uint32_t* r, uint32_t addr) {
    asm volatile("ldmatrix.sync.aligned.m8n8.x4.shared.b16 {%0,%1,%2,%3}, [%4];"
                 : "=r"(r[0]), "=r"(r[1]), "=r"(r[2]), "=r"(r[3]) : "r"(addr));
}

__device__ __forceinline__ void mma16816(float* c, const uint32_t* a, const uint32_t* b) {
    asm volatile(
        "mma.sync.aligned.m16n8k16.row.col.f32.bf16.bf16.f32 "
        "{%0,%1,%2,%3}, {%4,%5,%6,%7}, {%8,%9}, {%0,%1,%2,%3};"
        : "+f"(c[0]), "+f"(c[1]), "+f"(c[2]), "+f"(c[3])
        : "r"(a[0]), "r"(a[1]), "r"(a[2]), "r"(a[3]), "r"(b[0]), "r"(b[1]));
}

__device__ __forceinline__ void wsplit(const float* W, __nv_bfloat16* hi,
                                       __nv_bfloat16* lo, int NB, int idx) {
    int k = idx / NB, n = idx % NB;
    float v = W[idx];
    __nv_bfloat16 h = __float2bfloat16(v);
    __nv_bfloat16 l = __float2bfloat16(v - __bfloat162float(h));
    hi[n * 128 + k] = h;
    lo[n * 128 + k] = l;
}

// ---------------- prep: weight split x4 only (zeroing moved to memsets) ----------------
__global__ void k_prep(const float* __restrict__ W1, const float* __restrict__ W2,
                       const float* __restrict__ W3, const float* __restrict__ W4) {
    int g = blockIdx.x * blockDim.x + threadIdx.x;
    int stride = gridDim.x * blockDim.x;
    for (int i = g; i < 16384; i += stride) wsplit(W1, g_whi + 0,     g_wlo + 0,     128, i);
    for (int i = g; i < 16384; i += stride) wsplit(W2, g_whi + 16384, g_wlo + 16384, 128, i);
    for (int i = g; i < 16384; i += stride) wsplit(W3, g_whi + 32768, g_wlo + 32768, 128, i);
    for (int i = g; i < 8192;  i += stride) wsplit(W4, g_whi + 49152, g_wlo + 49152, 64,  i);
}

// ---------------- graph preprocessing ----------------
__global__ void k_count(const int* __restrict__ dst) {
    int e = blockIdx.x * blockDim.x + threadIdx.x;
    if (e < N_EDGES) atomicAdd(&g_cnt[dst[e]], 1);
}

// parallel 3-phase scan, all coalesced
__global__ void k_scanA() {
    int b = blockIdx.x, t = threadIdx.x;
    int s0 = b * SCAN_CH, s1 = min(s0 + SCAN_CH, N_NODES);
    int sum = 0;
    for (int i = s0 + t; i < s1; i += 256) sum += g_cnt[i];
    __shared__ int red[8];
    #pragma unroll
    for (int o = 16; o; o >>= 1) sum += __shfl_down_sync(0xFFFFFFFFu, sum, o);
    if ((t & 31) == 0) red[t >> 5] = sum;
    __syncthreads();
    if (t == 0) {
        int tot = 0;
        #pragma unroll
        for (int i = 0; i < 8; i++) tot += red[i];
        g_part[b] = tot;
    }
}

__global__ void k_scanB() {
    if (threadIdx.x == 0) {
        int run = 0;
        for (int b = 0; b < SCAN_BLOCKS; b++) {
            int v = g_part[b];
            g_part[b] = run;
            run += v;
        }
    }
}

__global__ void k_scanC() {
    int b = blockIdx.x, t = threadIdx.x;
    int s0 = b * SCAN_CH;
    int n = min(s0 + SCAN_CH, N_NODES) - s0;   // may be <0 never (64*782=50048)
    __shared__ int sc[1024];
    __shared__ int wtot[8];
    for (int i = t; i < 1024; i += 256) sc[i] = (i < n) ? g_cnt[s0 + i] : 0;
    __syncthreads();
    int s = sc[4 * t] + sc[4 * t + 1] + sc[4 * t + 2] + sc[4 * t + 3];
    // inclusive warp scan
    int incl = s;
    int lane = t & 31, wid = t >> 5;
    #pragma unroll
    for (int o = 1; o < 32; o <<= 1) {
        int u = __shfl_up_sync(0xFFFFFFFFu, incl, o);
        if (lane >= o) incl += u;
    }
    if (lane == 31) wtot[wid] = incl;
    __syncthreads();
    if (wid == 0 && lane < 8) {
        int wv = wtot[lane];
        #pragma unroll
        for (int o = 1; o < 8; o <<= 1) {
            int u = __shfl_up_sync(0xFFu, wv, o);
            if (lane >= o) wv += u;
        }
        wtot[lane] = wv;
    }
    __syncthreads();
    int base = g_part[b] + incl - s + (wid > 0 ? wtot[wid - 1] : 0);
    #pragma unroll
    for (int j = 0; j < 4; j++) {
        int i = 4 * t + j;
        if (i < n) {
            int c = sc[i];
            g_rowptr[s0 + i] = base;
            g_cursor[s0 + i] = base;
            g_dinv[s0 + i] = rsqrtf((float)c + 1.0f);
            base += c;
        }
    }
    if (b == SCAN_BLOCKS - 1 && t == 0) g_rowptr[N_NODES] = N_EDGES;
}

// scatter: packed (idx, weight) single STG.64
__global__ void k_scatter(const int* __restrict__ src, const int* __restrict__ dst) {
    int e = blockIdx.x * blockDim.x + threadIdx.x;
    if (e < N_EDGES) {
        int s = src[e], d = dst[e];
        int p = atomicAdd(&g_cursor[d], 1);
        g_csrwt[p] = make_uint2((uint32_t)s, __float_as_uint(g_dinv[s] * g_dinv[d]));
    }
}

// ---------------- HMMA GEMM: H[N,NBTOT](fp16) = act(X[N,128]) @ W[128,NBTOT] ----------------
template <int NBTOT>
__global__ void __launch_bounds__(512) k_mma_gemm(
    const float* __restrict__ X,
    const __nv_bfloat16* __restrict__ Bhi_g,
    const __nv_bfloat16* __restrict__ Blo_g,
    __half* __restrict__ H,
    const float* __restrict__ gamma, const float* __restrict__ beta, int layer) {
    constexpr int AS = 136;
    constexpr int NT = 4;

    extern __shared__ __nv_bfloat16 sm[];
    __nv_bfloat16* Ah = sm;
    __nv_bfloat16* Al = Ah + 128 * AS;
    __nv_bfloat16* Bh = Al + 128 * AS;
    __nv_bfloat16* Bl = Bh + 64 * AS;
    __shared__ float ss[128], sh[128];

    int tid = threadIdx.x, lane = tid & 31, w = tid >> 5;
    int rb = blockIdx.x * 128;
    int cb = blockIdx.y * 64;

    if (layer >= 0) {
        if (tid < 128) {
            float s = 0.f, q = 0.f;
            #pragma unroll
            for (int j = 0; j < 8; j++) {
                s += g_bnsum[layer][j][tid];
                q += g_bnsq[layer][j][tid];
            }
            float mu = s * (1.0f / N_NODES);
            float var = fmaxf(q * (1.0f / N_NODES) - mu * mu, 0.f);
            float sc = gamma[tid] * rsqrtf(var + BN_EPS);
            ss[tid] = sc;
            sh[tid] = beta[tid] - mu * sc;
        }
        __syncthreads();
    }

    for (int c = tid; c < 64 * 16; c += 512) {
        int n = c >> 4, s = c & 15;
        *(uint4*)(Bh + n * AS + s * 8) = ((const uint4*)Bhi_g)[(cb + n) * 16 + s];
        *(uint4*)(Bl + n * AS + s * 8) = ((const uint4*)Blo_g)[(cb + n) * 16 + s];
    }

    #pragma unroll
    for (int i = 0; i < 8; i++) {
        int idx = tid + i * 512;
        int row = idx >> 5, q = idx & 31;
        int r = rb + row;
        float4 v = make_float4(0.f, 0.f, 0.f, 0.f);
        if (r < N_NODES) {
            v = ((const float4*)X)[(size_t)r * 32 + q];
            if (layer >= 0) {
                int k = q * 4;
                v.x = fmaxf(fmaf(v.x, ss[k + 0], sh[k + 0]), 0.f);
                v.y = fmaxf(fmaf(v.y, ss[k + 1], sh[k + 1]), 0.f);
                v.z = fmaxf(fmaf(v.z, ss[k + 2], sh[k + 2]), 0.f);
                v.w = fmaxf(fmaf(v.w, ss[k + 3], sh[k + 3]), 0.f);
            }
        }
        float hx = __bfloat162float(__float2bfloat16(v.x));
        float hy = __bfloat162float(__float2bfloat16(v.y));
        float hz = __bfloat162float(__float2bfloat16(v.z));
        float hw = __bfloat162float(__float2bfloat16(v.w));
        uint32_t h01 = packbf(v.x, v.y), h23 = packbf(v.z, v.w);
        uint32_t l01 = packbf(v.x - hx, v.y - hy), l23 = packbf(v.z - hz, v.w - hw);
        *(uint2*)(Ah + row * AS + q * 4) = make_uint2(h01, h23);
        *(uint2*)(Al + row * AS + q * 4) = make_uint2(l01, l23);
    }
    __syncthreads();

    int mrow = (w & 7) * 16;
    int ncol = (w >> 3) * 32;

    uint32_t offA = ((mrow + (lane & 15)) * AS + ((lane >> 4) << 3)) * 2;
    uint32_t aAh = (uint32_t)__cvta_generic_to_shared(Ah) + offA;
    uint32_t aAl = (uint32_t)__cvta_generic_to_shared(Al) + offA;

    uint32_t aBh[NT / 2], aBl[NT / 2];
    #pragma unroll
    for (int p = 0; p < NT / 2; p++) {
        int n = ncol + p * 16 + (lane & 7) + ((lane >> 4) << 3);
        uint32_t offB = (n * AS + (((lane >> 3) & 1) << 3)) * 2;
        aBh[p] = (uint32_t)__cvta_generic_to_shared(Bh) + offB;
        aBl[p] = (uint32_t)__cvta_generic_to_shared(Bl) + offB;
    }

    float acc[NT][4];
    #pragma unroll
    for (int t = 0; t < NT; t++)
        #pragma unroll
        for (int j = 0; j < 4; j++) acc[t][j] = 0.f;

    #pragma unroll
    for (int kk = 0; kk < 8; kk++) {
        uint32_t kb = kk * 32;
        uint32_t ah[4], al[4];
        ldsm4(ah, aAh + kb);
        ldsm4(al, aAl + kb);
        #pragma unroll
        for (int p = 0; p < NT / 2; p++) {
            uint32_t bh[4], bl[4];
            ldsm4(bh, aBh[p] + kb);
            ldsm4(bl, aBl[p] + kb);
            mma16816(acc[2 * p],     ah, bh);
            mma16816(acc[2 * p + 1], ah, bh + 2);
            mma16816(acc[2 * p],     ah, bl);
            mma16816(acc[2 * p + 1], ah, bl + 2);
            mma16816(acc[2 * p],     al, bh);
            mma16816(acc[2 * p + 1], al, bh + 2);
        }
    }

    int r0 = rb + mrow + (lane >> 2);
    int r1 = r0 + 8;
    int cbase = cb + ncol + (lane & 3) * 2;
    #pragma unroll
    for (int t = 0; t < NT; t++) {
        int c = cbase + t * 8;
        if (r0 < N_NODES)
            *(__half2*)(H + (size_t)r0 * NBTOT + c) = __floats2half2_rn(acc[t][0], acc[t][1]);
        if (r1 < N_NODES)
            *(__half2*)(H + (size_t)r1 * NBTOT + c) = __floats2half2_rn(acc[t][2], acc[t][3]);
    }
}

// ---------------- aggregation: warp/node, packed edge stream, vector epilogue ----------------
template <int F, int DOBN>
__global__ void __launch_bounds__(256) k_agg(
    const __half* __restrict__ H, const float* __restrict__ bias,
    float* __restrict__ OUT, int layer) {
    constexpr int CPT = F / 32;
    __shared__ float sS[F], sQ[F];
    int tid = threadIdx.x, lane = tid & 31;
    if (DOBN) {
        if (tid < F) { sS[tid] = 0.f; sQ[tid] = 0.f; }
        __syncthreads();
    }
    int gw = (blockIdx.x * blockDim.x + tid) >> 5;
    float o[CPT];
    #pragma unroll
    for (int j = 0; j < CPT; j++) o[j] = 0.f;
    if (gw < N_NODES) {
        float dn = g_dinv[gw];
        float acc[CPT];
        {
            float sw = dn * dn;
            if constexpr (CPT == 4) {
                uint2 u = ((const uint2*)(H + (size_t)gw * F))[lane];
                float2 f0 = __half22float2(*(__half2*)&u.x);
                float2 f1 = __half22float2(*(__half2*)&u.y);
                acc[0] = f0.x * sw; acc[1] = f0.y * sw;
                acc[2] = f1.x * sw; acc[3] = f1.y * sw;
            } else {
                float2 f = __half22float2(((const __half2*)(H + (size_t)gw * F))[lane]);
                acc[0] = f.x * sw; acc[1] = f.y * sw;
            }
        }
        int b0 = g_rowptr[gw], b1 = g_rowptr[gw + 1];
        int i = b0;
        for (; i + 4 <= b1; i += 4) {
            uint2 e0 = g_csrwt[i], e1 = g_csrwt[i + 1], e2 = g_csrwt[i + 2], e3 = g_csrwt[i + 3];
            float w0 = __uint_as_float(e0.y), w1 = __uint_as_float(e1.y);
            float w2 = __uint_as_float(e2.y), w3 = __uint_as_float(e3.y);
            if constexpr (CPT == 4) {
                uint2 u0 = ((const uint2*)(H + (size_t)e0.x * F))[lane];
                uint2 u1 = ((const uint2*)(H + (size_t)e1.x * F))[lane];
                uint2 u2 = ((const uint2*)(H + (size_t)e2.x * F))[lane];
                uint2 u3 = ((const uint2*)(H + (size_t)e3.x * F))[lane];
                float2 a, b;
                a = __half22float2(*(__half2*)&u0.x); b = __half22float2(*(__half2*)&u0.y);
                acc[0] = fmaf(a.x, w0, acc[0]); acc[1] = fmaf(a.y, w0, acc[1]);
                acc[2] = fmaf(b.x, w0, acc[2]); acc[3] = fmaf(b.y, w0, acc[3]);
                a = __half22float2(*(__half2*)&u1.x); b = __half22float2(*(__half2*)&u1.y);
                acc[0] = fmaf(a.x, w1, acc[0]); acc[1] = fmaf(a.y, w1, acc[1]);
                acc[2] = fmaf(b.x, w1, acc[2]); acc[3] = fmaf(b.y, w1, acc[3]);
                a = __half22float2(*(__half2*)&u2.x); b = __half22float2(*(__half2*)&u2.y);
                acc[0] = fmaf(a.x, w2, acc[0]); acc[1] = fmaf(a.y, w2, acc[1]);
                acc[2] = fmaf(b.x, w2, acc[2]); acc[3] = fmaf(b.y, w2, acc[3]);
                a = __half22float2(*(__half2*)&u3.x); b = __half22float2(*(__half2*)&u3.y);
                acc[0] = fmaf(a.x, w3, acc[0]); acc[1] = fmaf(a.y, w3, acc[1]);
                acc[2] = fmaf(b.x, w3, acc[2]); acc[3] = fmaf(b.y, w3, acc[3]);
            } else {
                float2 f;
                f = __half22float2(((const __half2*)(H + (size_t)e0.x * F))[lane]);
                acc[0] = fmaf(f.x, w0, acc[0]); acc[1] = fmaf(f.y, w0, acc[1]);
                f = __half22float2(((const __half2*)(H + (size_t)e1.x * F))[lane]);
                acc[0] = fmaf(f.x, w1, acc[0]); acc[1] = fmaf(f.y, w1, acc[1]);
                f = __half22float2(((const __half2*)(H + (size_t)e2.x * F))[lane]);
                acc[0] = fmaf(f.x, w2, acc[0]); acc[1] = fmaf(f.y, w2, acc[1]);
                f = __half22float2(((const __half2*)(H + (size_t)e3.x * F))[lane]);
                acc[0] = fmaf(f.x, w3, acc[0]); acc[1] = fmaf(f.y, w3, acc[1]);
            }
        }
        for (; i < b1; i++) {
            uint2 e = g_csrwt[i];
            float wgt = __uint_as_float(e.y);
            if constexpr (CPT == 4) {
                uint2 u = ((const uint2*)(H + (size_t)e.x * F))[lane];
                float2 a = __half22float2(*(__half2*)&u.x);
                float2 b = __half22float2(*(__half2*)&u.y);
                acc[0] = fmaf(a.x, wgt, acc[0]); acc[1] = fmaf(a.y, wgt, acc[1]);
                acc[2] = fmaf(b.x, wgt, acc[2]); acc[3] = fmaf(b.y, wgt, acc[3]);
            } else {
                float2 f = __half22float2(((const __half2*)(H + (size_t)e.x * F))[lane]);
                acc[0] = fmaf(f.x, wgt, acc[0]); acc[1] = fmaf(f.y, wgt, acc[1]);
            }
        }
        if constexpr (CPT == 4) {
            float4 bv = ((const float4*)bias)[lane];
            o[0] = acc[0] + bv.x; o[1] = acc[1] + bv.y;
            o[2] = acc[2] + bv.z; o[3] = acc[3] + bv.w;
            ((float4*)(OUT + (size_t)gw * F))[lane] = make_float4(o[0], o[1], o[2], o[3]);
        } else {
            float2 bv = ((const float2*)bias)[lane];
            o[0] = acc[0] + bv.x; o[1] = acc[1] + bv.y;
            ((float2*)(OUT + (size_t)gw * F))[lane] = make_float2(o[0], o[1]);
        }
    }
    if (DOBN) {
        #pragma unroll
        for (int j = 0; j < CPT; j++) {
            atomicAdd(&sS[lane * CPT + j], o[j]);
            atomicAdd(&sQ[lane * CPT + j], o[j] * o[j]);
        }
        __syncthreads();
        int slot = blockIdx.x & 7;
        if (tid < F) {
            atomicAdd(&g_bnsum[layer][slot][tid], sS[tid]);
            atomicAdd(&g_bnsq[layer][slot][tid], sQ[tid]);
        }
    }
}

// ---------------- launcher ----------------
extern "C" void kernel_launch(void* const* d_in, const int* in_sizes, int n_in,
                              void* d_out, int out_size) {
    const float* x   = (const float*)d_in[0];
    const int*   ei  = (const int*)d_in[1];
    const int*   src = ei;
    const int*   dst = ei + N_EDGES;
    const float* W1 = (const float*)d_in[2];
    const float* b1 = (const float*)d_in[3];
    const float* W2 = (const float*)d_in[4];
    const float* b2 = (const float*)d_in[5];
    const float* W3 = (const float*)d_in[6];
    const float* b3 = (const float*)d_in[7];
    const float* W4 = (const float*)d_in[8];
    const float* b4 = (const float*)d_in[9];
    const float* g1 = (const float*)d_in[10];
    const float* be1 = (const float*)d_in[11];
    const float* g2 = (const float*)d_in[12];
    const float* be2 = (const float*)d_in[13];
    const float* g3 = (const float*)d_in[14];
    const float* be3 = (const float*)d_in[15];
    float* out = (float*)d_out;

    // resolve true device addresses (host shadow symbols route via ATS/C2C!)
    void* p;
    cudaGetSymbolAddress(&p, g_h);     __half* d_h  = (__half*)p;
    cudaGetSymbolAddress(&p, g_agg);   float* d_agg = (float*)p;
    cudaGetSymbolAddress(&p, g_whi);   __nv_bfloat16* whi = (__nv_bfloat16*)p;
    cudaGetSymbolAddress(&p, g_wlo);   __nv_bfloat16* wlo = (__nv_bfloat16*)p;
    cudaGetSymbolAddress(&p, g_cnt);   void* d_cnt = p;
    cudaGetSymbolAddress(&p, g_bnsum); void* d_bns = p;
    cudaGetSymbolAddress(&p, g_bnsq);  void* d_bnq = p;

    const int smemG = (2 * 128 * 136 + 2 * 64 * 136) * 2;  // 104448
    cudaFuncSetAttribute(k_mma_gemm<128>, cudaFuncAttributeMaxDynamicSharedMemorySize, smemG);
    cudaFuncSetAttribute(k_mma_gemm<64>,  cudaFuncAttributeMaxDynamicSharedMemorySize, smemG);

    const dim3 gblk128((N_NODES + 127) / 128, 2);
    const dim3 gblk64((N_NODES + 127) / 128, 1);
    const int ablk = (N_NODES + 7) / 8;

    // zeroing via memset nodes (graph-capturable, no kernel launch cost)
    cudaMemsetAsync(d_cnt, 0, N_NODES * sizeof(int));
    cudaMemsetAsync(d_bns, 0, 3 * 8 * 128 * sizeof(float));
    cudaMemsetAsync(d_bnq, 0, 3 * 8 * 128 * sizeof(float));

    // prep + CSR build (parallel scan); layer-1 GEMM interleaved
    k_prep<<<64, 256>>>(W1, W2, W3, W4);
    k_count<<<(N_EDGES + 255) / 256, 256>>>(dst);
    k_scanA<<<SCAN_BLOCKS, 256>>>();
    k_scanB<<<1, 32>>>();
    k_scanC<<<SCAN_BLOCKS, 256>>>();
    k_mma_gemm<128><<<gblk128, 512, smemG>>>(x, whi + 0, wlo + 0, d_h, g1, be1, -1);
    k_scatter<<<(N_EDGES + 255) / 256, 256>>>(src, dst);

    // layer 1: agg + fused BN stats(0)
    k_agg<128, 1><<<ablk, 256>>>(d_h, b1, d_agg, 0);
    // layer 2: GEMM (BN finalize(0) + ReLU fused), agg + BN stats(1)
    k_mma_gemm<128><<<gblk128, 512, smemG>>>(d_agg, whi + 16384, wlo + 16384, d_h, g1, be1, 0);
    k_agg<128, 1><<<ablk, 256>>>(d_h, b2, d_agg, 1);
    // layer 3
    k_mma_gemm<128><<<gblk128, 512, smemG>>>(d_agg, whi + 32768, wlo + 32768, d_h, g2, be2, 1);
    k_agg<128, 1><<<ablk, 256>>>(d_h, b3, d_agg, 2);
    // layer 4 (OUT=64), final agg writes d_out, no BN
    k_mma_gemm<64><<<gblk64, 512, smemG>>>(d_agg, whi + 49152, wlo + 49152, d_h, g3, be3, 2);
    k_agg<64, 0><<<ablk, 256>>>(d_h, b4, out, 0);
}

// round 13
// speedup vs baseline: 1.5197x; 1.0016x over previous
#include <cuda_runtime.h>
#include <cuda_bf16.h>
#include <cuda_fp16.h>
#include <cstdint>

#define N_NODES 50000
#define N_EDGES 800000
#define BN_EPS 1e-5f
#define SCAN_BLOCKS 64
#define SCAN_CH 782   // ceil(50000/64)

// ---------------- device scratch (no allocations allowed) ----------------
__device__ __half g_h[(size_t)N_NODES * 128];   // GEMM output (fp16 gather operand)
__device__ float g_agg[(size_t)N_NODES * 128];  // aggregation output (fp32)
__device__ float g_dinv[N_NODES];
__device__ int   g_rowptr[N_NODES + 1];
__device__ int   g_cursor[N_NODES];
__device__ uint2 g_csrwt[N_EDGES];              // packed (src_idx, weight_bits)
__device__ int   g_cnt[N_NODES];
__device__ int   g_part[SCAN_BLOCKS];
__device__ float g_bnsum[3][8][128];            // 8 slots to cut atomic chains
__device__ float g_bnsq[3][8][128];
// bf16 split weights, transposed to B[n][k] row-major (k contiguous, K=128).
__device__ __nv_bfloat16 g_whi[57344];
__device__ __nv_bfloat16 g_wlo[57344];

// ---------------- helpers ----------------
__device__ __forceinline__ uint32_t packbf(float a, float b) {
    __nv_bfloat162 t = __floats2bfloat162_rn(a, b);
    return *(uint32_t*)&t;
}

__device__ __forceinline__ void ldsm4(uint32_t* r, uint32_t addr) {
    asm volatile("ldmatrix.sync.aligned.m8n8.x4.shared.b16 {%0,%1,%2,%3}, [%4];"
                 : "=r"(r[0]), "=r"(r[1]), "=r"(r[2]), "=r"(r[3]) : "r"(addr));
}

__device__ __forceinline__ void mma16816(float* c, const uint32_t* a, const uint32_t* b) {
    asm volatile(
        "mma.sync.aligned.m16n8k16.row.col.f32.bf16.bf16.f32 "
        "{%0,%1,%2,%3}, {%4,%5,%6,%7}, {%8,%9}, {%0,%1,%2,%3};"
        : "+f"(c[0]), "+f"(c[1]), "+f"(c[2]), "+f"(c[3])
        : "r"(a[0]), "r"(a[1]), "r"(a[2]), "r"(a[3]), "r"(b[0]), "r"(b[1]));
}

__device__ __forceinline__ void wsplit(const float* W, __nv_bfloat16* hi,
                                       __nv_bfloat16* lo, int NB, int idx) {
    int k = idx / NB, n = idx % NB;
    float v = W[idx];
    __nv_bfloat16 h = __float2bfloat16(v);
    __nv_bfloat16 l = __float2bfloat16(v - __bfloat162float(h));
    hi[n * 128 + k] = h;
    lo[n * 128 + k] = l;
}

// ---------------- prep: weight split x4 ----------------
__global__ void k_prep(const float* __restrict__ W1, const float* __restrict__ W2,
                       const float* __restrict__ W3, const float* __restrict__ W4) {
    int g = blockIdx.x * blockDim.x + threadIdx.x;
    int stride = gridDim.x * blockDim.x;
    for (int i = g; i < 16384; i += stride) wsplit(W1, g_whi + 0,     g_wlo + 0,     128, i);
    for (int i = g; i < 16384; i += stride) wsplit(W2, g_whi + 16384, g_wlo + 16384, 128, i);
    for (int i = g; i < 16384; i += stride) wsplit(W3, g_whi + 32768, g_wlo + 32768, 128, i);
    for (int i = g; i < 8192;  i += stride) wsplit(W4, g_whi + 49152, g_wlo + 49152, 64,  i);
}

// ---------------- graph preprocessing ----------------
__global__ void k_count(const int* __restrict__ dst) {
    int e = blockIdx.x * blockDim.x + threadIdx.x;
    if (e < N_EDGES) atomicAdd(&g_cnt[dst[e]], 1);
}

// phase A: per-chunk totals
__global__ void k_scanA() {
    int b = blockIdx.x, t = threadIdx.x;
    int s0 = b * SCAN_CH, s1 = min(s0 + SCAN_CH, N_NODES);
    int sum = 0;
    for (int i = s0 + t; i < s1; i += 256) sum += g_cnt[i];
    __shared__ int red[8];
    #pragma unroll
    for (int o = 16; o; o >>= 1) sum += __shfl_down_sync(0xFFFFFFFFu, sum, o);
    if ((t & 31) == 0) red[t >> 5] = sum;
    __syncthreads();
    if (t == 0) {
        int tot = 0;
        #pragma unroll
        for (int i = 0; i < 8; i++) tot += red[i];
        g_part[b] = tot;
    }
}

// phase C: per-block base (computed redundantly from raw partials) + local scan + writes
__global__ void k_scanC() {
    int b = blockIdx.x, t = threadIdx.x;
    int s0 = b * SCAN_CH;
    int n = min(s0 + SCAN_CH, N_NODES) - s0;
    __shared__ int sc[1024];
    __shared__ int wtot[8];
    __shared__ int sp[SCAN_BLOCKS];
    __shared__ int sbase;
    if (t < SCAN_BLOCKS) sp[t] = g_part[t];
    for (int i = t; i < 1024; i += 256) sc[i] = (i < n) ? g_cnt[s0 + i] : 0;
    __syncthreads();
    if (t == 0) {   // exclusive prefix of the 64 partials; only sp[b] needed
        int run = 0;
        #pragma unroll
        for (int i = 0; i < SCAN_BLOCKS; i++) {
            int v = sp[i];
            if (i == b) { sbase = run; break; }
            run += v;
        }
    }
    int s = sc[4 * t] + sc[4 * t + 1] + sc[4 * t + 2] + sc[4 * t + 3];
    int incl = s;
    int lane = t & 31, wid = t >> 5;
    #pragma unroll
    for (int o = 1; o < 32; o <<= 1) {
        int u = __shfl_up_sync(0xFFFFFFFFu, incl, o);
        if (lane >= o) incl += u;
    }
    if (lane == 31) wtot[wid] = incl;
    __syncthreads();
    if (wid == 0 && lane < 8) {
        int wv = wtot[lane];
        #pragma unroll
        for (int o = 1; o < 8; o <<= 1) {
            int u = __shfl_up_sync(0xFFu, wv, o);
            if (lane >= o) wv += u;
        }
        wtot[lane] = wv;
    }
    __syncthreads();
    int base = sbase + incl - s + (wid > 0 ? wtot[wid - 1] : 0);
    #pragma unroll
    for (int j = 0; j < 4; j++) {
        int i = 4 * t + j;
        if (i < n) {
            int c = sc[i];
            g_rowptr[s0 + i] = base;
            g_cursor[s0 + i] = base;
            g_dinv[s0 + i] = rsqrtf((float)c + 1.0f);
            base += c;
        }
    }
    if (b == SCAN_BLOCKS - 1 && t == 0) g_rowptr[N_NODES] = N_EDGES;
}

// scatter: packed (idx, weight) single STG.64
__global__ void k_scatter(const int* __restrict__ src, const int* __restrict__ dst) {
    int e = blockIdx.x * blockDim.x + threadIdx.x;
    if (e < N_EDGES) {
        int s = src[e], d = dst[e];
        int p = atomicAdd(&g_cursor[d], 1);
        g_csrwt[p] = make_uint2((uint32_t)s, __float_as_uint(g_dinv[s] * g_dinv[d]));
    }
}

// ---------------- HMMA GEMM: H[N,NBTOT](fp16) = act(X[N,128]) @ W[128,NBTOT] ----------------
template <int NBTOT>
__global__ void __launch_bounds__(512) k_mma_gemm(
    const float* __restrict__ X,
    const __nv_bfloat16* __restrict__ Bhi_g,
    const __nv_bfloat16* __restrict__ Blo_g,
    __half* __restrict__ H,
    const float* __restrict__ gamma, const float* __restrict__ beta, int layer) {
    constexpr int AS = 136;
    constexpr int NT = 4;

    extern __shared__ __nv_bfloat16 sm[];
    __nv_bfloat16* Ah = sm;
    __nv_bfloat16* Al = Ah + 128 * AS;
    __nv_bfloat16* Bh = Al + 128 * AS;
    __nv_bfloat16* Bl = Bh + 64 * AS;
    __shared__ float ss[128], sh[128];

    int tid = threadIdx.x, lane = tid & 31, w = tid >> 5;
    int rb = blockIdx.x * 128;
    int cb = blockIdx.y * 64;

    if (layer >= 0) {
        if (tid < 128) {
            float s = 0.f, q = 0.f;
            #pragma unroll
            for (int j = 0; j < 8; j++) {
                s += g_bnsum[layer][j][tid];
                q += g_bnsq[layer][j][tid];
            }
            float mu = s * (1.0f / N_NODES);
            float var = fmaxf(q * (1.0f / N_NODES) - mu * mu, 0.f);
            float sc = gamma[tid] * rsqrtf(var + BN_EPS);
            ss[tid] = sc;
            sh[tid] = beta[tid] - mu * sc;
        }
        __syncthreads();
    }

    for (int c = tid; c < 64 * 16; c += 512) {
        int n = c >> 4, s = c & 15;
        *(uint4*)(Bh + n * AS + s * 8) = ((const uint4*)Bhi_g)[(cb + n) * 16 + s];
        *(uint4*)(Bl + n * AS + s * 8) = ((const uint4*)Blo_g)[(cb + n) * 16 + s];
    }

    #pragma unroll
    for (int i = 0; i < 8; i++) {
        int idx = tid + i * 512;
        int row = idx >> 5, q = idx & 31;
        int r = rb + row;
        float4 v = make_float4(0.f, 0.f, 0.f, 0.f);
        if (r < N_NODES) {
            v = ((const float4*)X)[(size_t)r * 32 + q];
            if (layer >= 0) {
                int k = q * 4;
                v.x = fmaxf(fmaf(v.x, ss[k + 0], sh[k + 0]), 0.f);
                v.y = fmaxf(fmaf(v.y, ss[k + 1], sh[k + 1]), 0.f);
                v.z = fmaxf(fmaf(v.z, ss[k + 2], sh[k + 2]), 0.f);
                v.w = fmaxf(fmaf(v.w, ss[k + 3], sh[k + 3]), 0.f);
            }
        }
        float hx = __bfloat162float(__float2bfloat16(v.x));
        float hy = __bfloat162float(__float2bfloat16(v.y));
        float hz = __bfloat162float(__float2bfloat16(v.z));
        float hw = __bfloat162float(__float2bfloat16(v.w));
        uint32_t h01 = packbf(v.x, v.y), h23 = packbf(v.z, v.w);
        uint32_t l01 = packbf(v.x - hx, v.y - hy), l23 = packbf(v.z - hz, v.w - hw);
        *(uint2*)(Ah + row * AS + q * 4) = make_uint2(h01, h23);
        *(uint2*)(Al + row * AS + q * 4) = make_uint2(l01, l23);
    }
    __syncthreads();

    int mrow = (w & 7) * 16;
    int ncol = (w >> 3) * 32;

    uint32_t offA = ((mrow + (lane & 15)) * AS + ((lane >> 4) << 3)) * 2;
    uint32_t aAh = (uint32_t)__cvta_generic_to_shared(Ah) + offA;
    uint32_t aAl = (uint32_t)__cvta_generic_to_shared(Al) + offA;

    uint32_t aBh[NT / 2], aBl[NT / 2];
    #pragma unroll
    for (int p = 0; p < NT / 2; p++) {
        int n = ncol + p * 16 + (lane & 7) + ((lane >> 4) << 3);
        uint32_t offB = (n * AS + (((lane >> 3) & 1) << 3)) * 2;
        aBh[p] = (uint32_t)__cvta_generic_to_shared(Bh) + offB;
        aBl[p] = (uint32_t)__cvta_generic_to_shared(Bl) + offB;
    }

    float acc[NT][4];
    #pragma unroll
    for (int t = 0; t < NT; t++)
        #pragma unroll
        for (int j = 0; j < 4; j++) acc[t][j] = 0.f;

    #pragma unroll
    for (int kk = 0; kk < 8; kk++) {
        uint32_t kb = kk * 32;
        uint32_t ah[4], al[4];
        ldsm4(ah, aAh + kb);
        ldsm4(al, aAl + kb);
        #pragma unroll
        for (int p = 0; p < NT / 2; p++) {
            uint32_t bh[4], bl[4];
            ldsm4(bh, aBh[p] + kb);
            ldsm4(bl, aBl[p] + kb);
            mma16816(acc[2 * p],     ah, bh);
            mma16816(acc[2 * p + 1], ah, bh + 2);
            mma16816(acc[2 * p],     ah, bl);
            mma16816(acc[2 * p + 1], ah, bl + 2);
            mma16816(acc[2 * p],     al, bh);
            mma16816(acc[2 * p + 1], al, bh + 2);
        }
    }

    int r0 = rb + mrow + (lane >> 2);
    int r1 = r0 + 8;
    int cbase = cb + ncol + (lane & 3) * 2;
    #pragma unroll
    for (int t = 0; t < NT; t++) {
        int c = cbase + t * 8;
        if (r0 < N_NODES)
            *(__half2*)(H + (size_t)r0 * NBTOT + c) = __floats2half2_rn(acc[t][0], acc[t][1]);
        if (r1 < N_NODES)
            *(__half2*)(H + (size_t)r1 * NBTOT + c) = __floats2half2_rn(acc[t][2], acc[t][3]);
    }
}

// ---------------- aggregation: warp/node, packed edge stream, vector epilogue ----------------
template <int F, int DOBN>
__global__ void __launch_bounds__(256) k_agg(
    const __half* __restrict__ H, const float* __restrict__ bias,
    float* __restrict__ OUT, int layer) {
    constexpr int CPT = F / 32;
    __shared__ float sS[F], sQ[F];
    int tid = threadIdx.x, lane = tid & 31;
    if (DOBN) {
        if (tid < F) { sS[tid] = 0.f; sQ[tid] = 0.f; }
        __syncthreads();
    }
    int gw = (blockIdx.x * blockDim.x + tid) >> 5;
    float o[CPT];
    #pragma unroll
    for (int j = 0; j < CPT; j++) o[j] = 0.f;
    if (gw < N_NODES) {
        float dn = g_dinv[gw];
        float acc[CPT];
        {
            float sw = dn * dn;
            if constexpr (CPT == 4) {
                uint2 u = ((const uint2*)(H + (size_t)gw * F))[lane];
                float2 f0 = __half22float2(*(__half2*)&u.x);
                float2 f1 = __half22float2(*(__half2*)&u.y);
                acc[0] = f0.x * sw; acc[1] = f0.y * sw;
                acc[2] = f1.x * sw; acc[3] = f1.y * sw;
            } else {
                float2 f = __half22float2(((const __half2*)(H + (size_t)gw * F))[lane]);
                acc[0] = f.x * sw; acc[1] = f.y * sw;
            }
        }
        int b0 = g_rowptr[gw], b1 = g_rowptr[gw + 1];
        int i = b0;
        for (; i + 4 <= b1; i += 4) {
            uint2 e0 = g_csrwt[i], e1 = g_csrwt[i + 1], e2 = g_csrwt[i + 2], e3 = g_csrwt[i + 3];
            float w0 = __uint_as_float(e0.y), w1 = __uint_as_float(e1.y);
            float w2 = __uint_as_float(e2.y), w3 = __uint_as_float(e3.y);
            if constexpr (CPT == 4) {
                uint2 u0 = ((const uint2*)(H + (size_t)e0.x * F))[lane];
                uint2 u1 = ((const uint2*)(H + (size_t)e1.x * F))[lane];
                uint2 u2 = ((const uint2*)(H + (size_t)e2.x * F))[lane];
                uint2 u3 = ((const uint2*)(H + (size_t)e3.x * F))[lane];
                float2 a, b;
                a = __half22float2(*(__half2*)&u0.x); b = __half22float2(*(__half2*)&u0.y);
                acc[0] = fmaf(a.x, w0, acc[0]); acc[1] = fmaf(a.y, w0, acc[1]);
                acc[2] = fmaf(b.x, w0, acc[2]); acc[3] = fmaf(b.y, w0, acc[3]);
                a = __half22float2(*(__half2*)&u1.x); b = __half22float2(*(__half2*)&u1.y);
                acc[0] = fmaf(a.x, w1, acc[0]); acc[1] = fmaf(a.y, w1, acc[1]);
                acc[2] = fmaf(b.x, w1, acc[2]); acc[3] = fmaf(b.y, w1, acc[3]);
                a = __half22float2(*(__half2*)&u2.x); b = __half22float2(*(__half2*)&u2.y);
                acc[0] = fmaf(a.x, w2, acc[0]); acc[1] = fmaf(a.y, w2, acc[1]);
                acc[2] = fmaf(b.x, w2, acc[2]); acc[3] = fmaf(b.y, w2, acc[3]);
                a = __half22float2(*(__half2*)&u3.x); b = __half22float2(*(__half2*)&u3.y);
                acc[0] = fmaf(a.x, w3, acc[0]); acc[1] = fmaf(a.y, w3, acc[1]);
                acc[2] = fmaf(b.x, w3, acc[2]); acc[3] = fmaf(b.y, w3, acc[3]);
            } else {
                float2 f;
                f = __half22float2(((const __half2*)(H + (size_t)e0.x * F))[lane]);
                acc[0] = fmaf(f.x, w0, acc[0]); acc[1] = fmaf(f.y, w0, acc[1]);
                f = __half22float2(((const __half2*)(H + (size_t)e1.x * F))[lane]);
                acc[0] = fmaf(f.x, w1, acc[0]); acc[1] = fmaf(f.y, w1, acc[1]);
                f = __half22float2(((const __half2*)(H + (size_t)e2.x * F))[lane]);
                acc[0] = fmaf(f.x, w2, acc[0]); acc[1] = fmaf(f.y, w2, acc[1]);
                f = __half22float2(((const __half2*)(H + (size_t)e3.x * F))[lane]);
                acc[0] = fmaf(f.x, w3, acc[0]); acc[1] = fmaf(f.y, w3, acc[1]);
            }
        }
        for (; i < b1; i++) {
            uint2 e = g_csrwt[i];
            float wgt = __uint_as_float(e.y);
            if constexpr (CPT == 4) {
                uint2 u = ((const uint2*)(H + (size_t)e.x * F))[lane];
                float2 a = __half22float2(*(__half2*)&u.x);
                float2 b = __half22float2(*(__half2*)&u.y);
                acc[0] = fmaf(a.x, wgt, acc[0]); acc[1] = fmaf(a.y, wgt, acc[1]);
                acc[2] = fmaf(b.x, wgt, acc[2]); acc[3] = fmaf(b.y, wgt, acc[3]);
            } else {
                float2 f = __half22float2(((const __half2*)(H + (size_t)e.x * F))[lane]);
                acc[0] = fmaf(f.x, wgt, acc[0]); acc[1] = fmaf(f.y, wgt, acc[1]);
            }
        }
        if constexpr (CPT == 4) {
            float4 bv = ((const float4*)bias)[lane];
            o[0] = acc[0] + bv.x; o[1] = acc[1] + bv.y;
            o[2] = acc[2] + bv.z; o[3] = acc[3] + bv.w;
            ((float4*)(OUT + (size_t)gw * F))[lane] = make_float4(o[0], o[1], o[2], o[3]);
        } else {
            float2 bv = ((const float2*)bias)[lane];
            o[0] = acc[0] + bv.x; o[1] = acc[1] + bv.y;
            ((float2*)(OUT + (size_t)gw * F))[lane] = make_float2(o[0], o[1]);
        }
    }
    if (DOBN) {
        #pragma unroll
        for (int j = 0; j < CPT; j++) {
            atomicAdd(&sS[lane * CPT + j], o[j]);
            atomicAdd(&sQ[lane * CPT + j], o[j] * o[j]);
        }
        __syncthreads();
        int slot = blockIdx.x & 7;
        if (tid < F) {
            atomicAdd(&g_bnsum[layer][slot][tid], sS[tid]);
            atomicAdd(&g_bnsq[layer][slot][tid], sQ[tid]);
        }
    }
}

// ---------------- launcher ----------------
extern "C" void kernel_launch(void* const* d_in, const int* in_sizes, int n_in,
                              void* d_out, int out_size) {
    const float* x   = (const float*)d_in[0];
    const int*   ei  = (const int*)d_in[1];
    const int*   src = ei;
    const int*   dst = ei + N_EDGES;
    const float* W1 = (const float*)d_in[2];
    const float* b1 = (const float*)d_in[3];
    const float* W2 = (const float*)d_in[4];
    const float* b2 = (const float*)d_in[5];
    const float* W3 = (const float*)d_in[6];
    const float* b3 = (const float*)d_in[7];
    const float* W4 = (const float*)d_in[8];
    const float* b4 = (const float*)d_in[9];
    const float* g1 = (const float*)d_in[10];
    const float* be1 = (const float*)d_in[11];
    const float* g2 = (const float*)d_in[12];
    const float* be2 = (const float*)d_in[13];
    const float* g3 = (const float*)d_in[14];
    const float* be3 = (const float*)d_in[15];
    float* out = (float*)d_out;

    // resolve true device addresses (host shadow symbols route via ATS/C2C!)
    void* p;
    cudaGetSymbolAddress(&p, g_h);     __half* d_h  = (__half*)p;
    cudaGetSymbolAddress(&p, g_agg);   float* d_agg = (float*)p;
    cudaGetSymbolAddress(&p, g_whi);   __nv_bfloat16* whi = (__nv_bfloat16*)p;
    cudaGetSymbolAddress(&p, g_wlo);   __nv_bfloat16* wlo = (__nv_bfloat16*)p;
    cudaGetSymbolAddress(&p, g_cnt);   void* d_cnt = p;
    cudaGetSymbolAddress(&p, g_bnsum); void* d_bns = p;
    cudaGetSymbolAddress(&p, g_bnsq);  void* d_bnq = p;

    // side stream + events, created once on the first (uncaptured) call.
    // During graph capture these become branch edges in the captured graph.
    static cudaStream_t s2 = nullptr;
    static cudaEvent_t ev1 = nullptr, ev2 = nullptr;
    if (!s2) {
        cudaStreamCreateWithFlags(&s2, cudaStreamNonBlocking);
        cudaEventCreateWithFlags(&ev1, cudaEventDisableTiming);
        cudaEventCreateWithFlags(&ev2, cudaEventDisableTiming);
    }

    const int smemG = (2 * 128 * 136 + 2 * 64 * 136) * 2;  // 104448
    cudaFuncSetAttribute(k_mma_gemm<128>, cudaFuncAttributeMaxDynamicSharedMemorySize, smemG);
    cudaFuncSetAttribute(k_mma_gemm<64>,  cudaFuncAttributeMaxDynamicSharedMemorySize, smemG);

    const dim3 gblk128((N_NODES + 127) / 128, 2);
    const dim3 gblk64((N_NODES + 127) / 128, 1);
    const int ablk = (N_NODES + 7) / 8;

    // zeroing via memset nodes
    cudaMemsetAsync(d_cnt, 0, N_NODES * sizeof(int));
    cudaMemsetAsync(d_bns, 0, 3 * 8 * 128 * sizeof(float));
    cudaMemsetAsync(d_bnq, 0, 3 * 8 * 128 * sizeof(float));

    // fork: branch B (CSR build) on s2, branch A (prep + layer-1 GEMM) on main
    cudaEventRecord(ev1, 0);
    cudaStreamWaitEvent(s2, ev1, 0);
    k_count<<<(N_EDGES + 255) / 256, 256, 0, s2>>>(dst);
    k_scanA<<<SCAN_BLOCKS, 256, 0, s2>>>();
    k_scanC<<<SCAN_BLOCKS, 256, 0, s2>>>();
    k_scatter<<<(N_EDGES + 255) / 256, 256, 0, s2>>>(src, dst);
    cudaEventRecord(ev2, s2);

    k_prep<<<64, 256>>>(W1, W2, W3, W4);
    k_mma_gemm<128><<<gblk128, 512, smemG>>>(x, whi + 0, wlo + 0, d_h, g1, be1, -1);

    // join: everything below needs both branches
    cudaStreamWaitEvent(0, ev2, 0);

    // layer 1: agg + fused BN stats(0)
    k_agg<128, 1><<<ablk, 256>>>(d_h, b1, d_agg, 0);
    // layer 2: GEMM (BN finalize(0) + ReLU fused), agg + BN stats(1)
    k_mma_gemm<128><<<gblk128, 512, smemG>>>(d_agg, whi + 16384, wlo + 16384, d_h, g1, be1, 0);
    k_agg<128, 1><<<ablk, 256>>>(d_h, b2, d_agg, 1);
    // layer 3
    k_mma_gemm<128><<<gblk128, 512, smemG>>>(d_agg, whi + 32768, wlo + 32768, d_h, g2, be2, 1);
    k_agg<128, 1><<<ablk, 256>>>(d_h, b3, d_agg, 2);
    // layer 4 (OUT=64), final agg writes d_out, no BN
    k_mma_gemm<64><<<gblk64, 512, smemG>>>(d_agg, whi + 49152, wlo + 49152, d_h, g3, be3, 2);
    k_agg<64, 0><<<ablk, 256>>>(d_h, b4, out, 0);
}